// round 1
// baseline (speedup 1.0000x reference)
#include <cuda_runtime.h>

#define NN 100000
#define NE 3200000
#define NH 64

// ---------------- scratch (__device__ globals: allocation-free) ----------------
__device__ int   g_cnt[NN];
__device__ int   g_rowptr[NN + 1];
__device__ int   g_cursor[NN];
__device__ float g_dis[NN];
__device__ int2  g_edge[NE];            // .x = src node, .y = bit-cast edge weight
__device__ float g_bufA[NN * 192];
__device__ float g_bufB[NN * 192];
__device__ float g_bufC[NN * 192];
__device__ float g_acc[NN * NH];
__device__ float g_skip[NN * NH];
__device__ float g_h1[NN * NH];
__device__ float g_h2[NN * NH];

// ---------------- graph preprocessing ----------------
__global__ void hist_kernel(const int* __restrict__ dst, int* __restrict__ cnt, int E) {
    int i = blockIdx.x * blockDim.x + threadIdx.x;
    if (i < E) atomicAdd(&cnt[dst[i]], 1);
}

__global__ void dis_kernel(const int* __restrict__ cnt, float* __restrict__ dis, int n) {
    int i = blockIdx.x * blockDim.x + threadIdx.x;
    if (i < n) dis[i] = cnt[i] > 0 ? rsqrtf((float)cnt[i]) : 0.0f;
}

// single-block exclusive scan of cnt -> rowptr (also seeds cursor)
__global__ void scan_kernel(const int* __restrict__ cnt, int* __restrict__ rowptr,
                            int* __restrict__ cursor, int n) {
    __shared__ int wsum[32];
    __shared__ int carry;
    int tid = threadIdx.x;
    int lane = tid & 31, wid = tid >> 5;
    if (tid == 0) carry = 0;
    __syncthreads();
    for (int base = 0; base < n; base += 1024) {
        int i = base + tid;
        int v = (i < n) ? cnt[i] : 0;
        int x = v;
        #pragma unroll
        for (int o = 1; o < 32; o <<= 1) {
            int y = __shfl_up_sync(0xffffffffu, x, o);
            if (lane >= o) x += y;
        }
        if (lane == 31) wsum[wid] = x;
        __syncthreads();
        if (wid == 0) {
            int w = wsum[lane];
            #pragma unroll
            for (int o = 1; o < 32; o <<= 1) {
                int y = __shfl_up_sync(0xffffffffu, w, o);
                if (lane >= o) w += y;
            }
            wsum[lane] = w;
        }
        __syncthreads();
        int base_off = carry + (wid ? wsum[wid - 1] : 0);
        int excl = base_off + x - v;
        if (i < n) { rowptr[i] = excl; cursor[i] = excl; }
        int total = wsum[31];
        __syncthreads();
        if (tid == 0) carry += total;
        __syncthreads();
    }
    if (threadIdx.x == 0) rowptr[n] = carry;
}

__global__ void fill_kernel(const int* __restrict__ src, const int* __restrict__ dst,
                            const float* __restrict__ dis, int* __restrict__ cursor,
                            int2* __restrict__ edge, int E) {
    int i = blockIdx.x * blockDim.x + threadIdx.x;
    if (i < E) {
        int d = dst[i], s = src[i];
        int pos = atomicAdd(&cursor[d], 1);
        float w = dis[s] * dis[d];
        edge[pos] = make_int2(s, __float_as_int(w));
    }
}

// ---------------- pull-based propagation (CSR by dst) ----------------
// out[i,:] = scale * sum_{e in row i} w_e * tin[src_e, :]  (- tsub[i,:] if tsub)
// warp per node; F = 32 * VEC; coalesced float2 layout: element idx = j*32 + lane
template<int VEC>
__global__ void prop_kernel(const int* __restrict__ rowptr, const int2* __restrict__ edge,
                            const float* __restrict__ tin, const float* __restrict__ tsub,
                            float* __restrict__ tout, float scale, int n) {
    int gw = (blockIdx.x * blockDim.x + threadIdx.x) >> 5;
    if (gw >= n) return;
    int lane = threadIdx.x & 31;
    constexpr int F2 = 16 * VEC;   // floats2 per row
    constexpr int V2 = VEC / 2;
    int beg = __ldg(rowptr + gw), end = __ldg(rowptr + gw + 1);
    float2 acc[V2];
    #pragma unroll
    for (int j = 0; j < V2; j++) acc[j] = make_float2(0.f, 0.f);
    const float2* tin2 = (const float2*)tin;
    for (int p = beg; p < end; ++p) {
        int2 e = __ldg(edge + p);
        int s = e.x;
        float w = __int_as_float(e.y);
        const float2* row = tin2 + (size_t)s * F2;
        #pragma unroll
        for (int j = 0; j < V2; j++) {
            float2 t = __ldg(row + j * 32 + lane);
            acc[j].x += w * t.x;
            acc[j].y += w * t.y;
        }
    }
    float2* out2 = (float2*)tout + (size_t)gw * F2;
    if (tsub) {
        const float2* sub2 = (const float2*)tsub + (size_t)gw * F2;
        #pragma unroll
        for (int j = 0; j < V2; j++) {
            float2 sv = __ldg(sub2 + j * 32 + lane);
            out2[j * 32 + lane] = make_float2(scale * acc[j].x - sv.x,
                                              scale * acc[j].y - sv.y);
        }
    } else {
        #pragma unroll
        for (int j = 0; j < V2; j++)
            out2[j * 32 + lane] = make_float2(scale * acc[j].x, scale * acc[j].y);
    }
}

// ---------------- tiled fp32 GEMM: C[N,BN] (+)= A[N,KD] @ W[KD,BN] (+ bias) ----------------
template<int KD, int BN>
__global__ void gemm_kernel(const float* __restrict__ A, const float* __restrict__ W,
                            const float* __restrict__ bias, float* __restrict__ C,
                            int N, int accum) {
    constexpr int BM = 64, BK = 32;
    constexpr int TM = 4, TN = BN / 16;
    __shared__ float As[BK][BM + 1];   // stride 65: conflict-free transposed stores
    __shared__ float Bs[BK][BN];
    int block_row = blockIdx.x * BM;
    int tx = threadIdx.x & 15, ty = threadIdx.x >> 4;
    float acc[TM][TN];
    #pragma unroll
    for (int i = 0; i < TM; i++)
        #pragma unroll
        for (int j = 0; j < TN; j++) acc[i][j] = 0.f;

    for (int k0 = 0; k0 < KD; k0 += BK) {
        #pragma unroll
        for (int t = 0; t < (BM * BK) / 256; t++) {
            int idx = threadIdx.x + 256 * t;
            int r = idx >> 5, c = idx & 31;
            int gr = block_row + r;
            As[c][r] = (gr < N) ? __ldg(A + (size_t)gr * KD + k0 + c) : 0.f;
        }
        #pragma unroll
        for (int t = 0; t < (BK * BN) / 256; t++) {
            int idx = threadIdx.x + 256 * t;
            int r = idx / BN, c = idx % BN;
            Bs[r][c] = __ldg(W + (size_t)(k0 + r) * BN + c);
        }
        __syncthreads();
        #pragma unroll
        for (int kk = 0; kk < BK; kk++) {
            float a[TM], b[TN];
            #pragma unroll
            for (int i = 0; i < TM; i++) a[i] = As[kk][ty * TM + i];
            #pragma unroll
            for (int j = 0; j < TN; j++) b[j] = Bs[kk][tx * TN + j];
            #pragma unroll
            for (int i = 0; i < TM; i++)
                #pragma unroll
                for (int j = 0; j < TN; j++)
                    acc[i][j] += a[i] * b[j];
        }
        __syncthreads();
    }
    #pragma unroll
    for (int i = 0; i < TM; i++) {
        int gr = block_row + ty * TM + i;
        if (gr >= N) continue;
        #pragma unroll
        for (int j = 0; j < TN; j++) {
            int gc = tx * TN + j;
            float v = acc[i][j];
            if (bias) v += __ldg(bias + gc);
            size_t idx = (size_t)gr * BN + gc;
            if (accum) C[idx] += v; else C[idx] = v;
        }
    }
}

// ---------------- elementwise ----------------
__global__ void combine_kernel(const float* __restrict__ acc, const float* __restrict__ skip,
                               float* __restrict__ hout, int n) {
    int i = blockIdx.x * blockDim.x + threadIdx.x;
    if (i < n) hout[i] = fmaxf(acc[i], 0.f) + skip[i];
}

__global__ void concat_kernel(const float* __restrict__ h, const float* __restrict__ x,
                              float* __restrict__ Cc, int N) {
    int i = blockIdx.x * blockDim.x + threadIdx.x;
    if (i < N * 192) {
        int node = i / 192, j = i % 192;
        Cc[i] = (j < NH) ? h[(size_t)node * NH + j]
                         : x[(size_t)node * 128 + (j - NH)];
    }
}

// ---------------- host-side orchestration ----------------
static void run_prop(int vec, const int* rowptr, const int2* edge, const float* tin,
                     const float* tsub, float* tout, float scale) {
    int blocks = (NN * 32 + 255) / 256;
    switch (vec) {
        case 4: prop_kernel<4><<<blocks, 256>>>(rowptr, edge, tin, tsub, tout, scale, NN); break;
        case 2: prop_kernel<2><<<blocks, 256>>>(rowptr, edge, tin, tsub, tout, scale, NN); break;
        case 6: prop_kernel<6><<<blocks, 256>>>(rowptr, edge, tin, tsub, tout, scale, NN); break;
    }
}

static void run_gemm(int kd, const float* A, const float* W, const float* bias,
                     float* C, int accum) {
    int grid = (NN + 63) / 64;
    if (kd == 128) gemm_kernel<128, 64><<<grid, 256>>>(A, W, bias, C, NN, accum);
    else           gemm_kernel<64, 64><<<grid, 256>>>(A, W, bias, C, NN, accum);
}

static void cheb_layer(const float* h, int kd,
                       const float* W, const float* b,
                       const float* Ws, const float* bs,
                       float* hout,
                       const int* rowptr, const int2* edge,
                       float* bufs[3], float* acc, float* skip) {
    int vec = kd / 32;
    // k = 0
    run_gemm(kd, h, W, b, acc, 0);
    // k = 1: T1 = -L h
    run_prop(vec, rowptr, edge, h, nullptr, bufs[0], -1.f);
    run_gemm(kd, bufs[0], W + (size_t)1 * kd * NH, nullptr, acc, 1);
    const float* Tprev = h;
    const float* Tcur = bufs[0];
    int cur = 0;
    for (int k = 2; k < 6; k++) {
        int nxt = (cur + 1) % 3;
        // T2 = 2 * (-L T1) - T0
        run_prop(vec, rowptr, edge, Tcur, Tprev, bufs[nxt], -2.f);
        run_gemm(kd, bufs[nxt], W + (size_t)k * kd * NH, nullptr, acc, 1);
        Tprev = Tcur; Tcur = bufs[nxt]; cur = nxt;
    }
    // K=1 skip conv
    run_gemm(kd, h, Ws, bs, skip, 0);
    combine_kernel<<<(NN * NH + 255) / 256, 256>>>(acc, skip, hout, NN * NH);
}

extern "C" void kernel_launch(void* const* d_in, const int* in_sizes, int n_in,
                              void* d_out, int out_size) {
    const float* x   = (const float*)d_in[0];
    const int*   ei  = (const int*)d_in[1];
    const float* W0  = (const float*)d_in[2];
    const float* b0  = (const float*)d_in[3];
    const float* Ws0 = (const float*)d_in[4];
    const float* bs0 = (const float*)d_in[5];
    const float* W1  = (const float*)d_in[6];
    const float* b1  = (const float*)d_in[7];
    const float* Ws1 = (const float*)d_in[8];
    const float* bs1 = (const float*)d_in[9];
    const float* W2  = (const float*)d_in[10];
    const float* b2  = (const float*)d_in[11];
    const float* Ws2 = (const float*)d_in[12];
    const float* bs2 = (const float*)d_in[13];
    const float* Wm  = (const float*)d_in[14];
    const float* bm  = (const float*)d_in[15];
    float* out = (float*)d_out;

    const int* src = ei;
    const int* dst = ei + NE;

    void* p;
    cudaGetSymbolAddress(&p, g_cnt);    int*   cnt    = (int*)p;
    cudaGetSymbolAddress(&p, g_rowptr); int*   rowptr = (int*)p;
    cudaGetSymbolAddress(&p, g_cursor); int*   cursor = (int*)p;
    cudaGetSymbolAddress(&p, g_dis);    float* dis    = (float*)p;
    cudaGetSymbolAddress(&p, g_edge);   int2*  edge   = (int2*)p;
    cudaGetSymbolAddress(&p, g_bufA);   float* bufA   = (float*)p;
    cudaGetSymbolAddress(&p, g_bufB);   float* bufB   = (float*)p;
    cudaGetSymbolAddress(&p, g_bufC);   float* bufC   = (float*)p;
    cudaGetSymbolAddress(&p, g_acc);    float* acc    = (float*)p;
    cudaGetSymbolAddress(&p, g_skip);   float* skip   = (float*)p;
    cudaGetSymbolAddress(&p, g_h1);     float* h1     = (float*)p;
    cudaGetSymbolAddress(&p, g_h2);     float* h2     = (float*)p;

    float* bufs[3] = {bufA, bufB, bufC};

    // ---- preprocessing: degree, norm weights, CSR (sorted by dst) ----
    cudaMemsetAsync(cnt, 0, NN * sizeof(int), 0);
    hist_kernel<<<(NE + 255) / 256, 256>>>(dst, cnt, NE);
    dis_kernel<<<(NN + 255) / 256, 256>>>(cnt, dis, NN);
    scan_kernel<<<1, 1024>>>(cnt, rowptr, cursor, NN);
    fill_kernel<<<(NE + 255) / 256, 256>>>(src, dst, dis, cursor, edge, NE);

    // ---- 3 Kipf blocks ----
    cheb_layer(x,  128, W0, b0, Ws0, bs0, h1, rowptr, edge, bufs, acc, skip);
    cheb_layer(h1,  64, W1, b1, Ws1, bs1, h2, rowptr, edge, bufs, acc, skip);
    cheb_layer(h2,  64, W2, b2, Ws2, bs2, h1, rowptr, edge, bufs, acc, skip);

    // ---- mix head: concat(h, x) -> ChebConv K=2 -> out ----
    concat_kernel<<<(NN * 192 + 255) / 256, 256>>>(h1, x, bufA, NN);
    {
        int grid = (NN + 63) / 64;
        gemm_kernel<192, 32><<<grid, 256>>>(bufA, Wm, bm, out, NN, 0);
        run_prop(6, rowptr, edge, bufA, nullptr, bufB, -1.f);
        gemm_kernel<192, 32><<<grid, 256>>>(bufB, Wm + 192 * 32, nullptr, out, NN, 1);
    }
}

// round 2
// speedup vs baseline: 1.2832x; 1.2832x over previous
#include <cuda_runtime.h>

#define NN 100000
#define NE 3200000
#define NH 64

// ---------------- scratch (__device__ globals: allocation-free) ----------------
__device__ int   g_cnt[NN];
__device__ int   g_rowptr[NN + 1];
__device__ int   g_cursor[NN];
__device__ float g_dis[NN];
__device__ int2  g_edge[NE];            // .x = src node, .y = bit-cast edge weight
__device__ float g_C[(size_t)NN * 448]; // fused GEMM output: c_0..c_5 | skip
__device__ float g_b0[NN * NH];
__device__ float g_b1[NN * NH];
__device__ float g_b2[NN * NH];
__device__ float g_cat[NN * 192];
__device__ float g_h1[NN * NH];
__device__ float g_h2[NN * NH];

// ---------------- graph preprocessing ----------------
__global__ void hist_kernel(const int* __restrict__ dst, int* __restrict__ cnt, int E) {
    int i = blockIdx.x * blockDim.x + threadIdx.x;
    if (i < E) atomicAdd(&cnt[dst[i]], 1);
}

__global__ void dis_kernel(const int* __restrict__ cnt, float* __restrict__ dis, int n) {
    int i = blockIdx.x * blockDim.x + threadIdx.x;
    if (i < n) dis[i] = cnt[i] > 0 ? rsqrtf((float)cnt[i]) : 0.0f;
}

// single-block exclusive scan of cnt -> rowptr (also seeds cursor)
__global__ void scan_kernel(const int* __restrict__ cnt, int* __restrict__ rowptr,
                            int* __restrict__ cursor, int n) {
    __shared__ int wsum[32];
    __shared__ int carry;
    int tid = threadIdx.x;
    int lane = tid & 31, wid = tid >> 5;
    if (tid == 0) carry = 0;
    __syncthreads();
    for (int base = 0; base < n; base += 1024) {
        int i = base + tid;
        int v = (i < n) ? cnt[i] : 0;
        int x = v;
        #pragma unroll
        for (int o = 1; o < 32; o <<= 1) {
            int y = __shfl_up_sync(0xffffffffu, x, o);
            if (lane >= o) x += y;
        }
        if (lane == 31) wsum[wid] = x;
        __syncthreads();
        if (wid == 0) {
            int w = wsum[lane];
            #pragma unroll
            for (int o = 1; o < 32; o <<= 1) {
                int y = __shfl_up_sync(0xffffffffu, w, o);
                if (lane >= o) w += y;
            }
            wsum[lane] = w;
        }
        __syncthreads();
        int base_off = carry + (wid ? wsum[wid - 1] : 0);
        int excl = base_off + x - v;
        if (i < n) { rowptr[i] = excl; cursor[i] = excl; }
        int total = wsum[31];
        __syncthreads();
        if (tid == 0) carry += total;
        __syncthreads();
    }
    if (threadIdx.x == 0) rowptr[n] = carry;
}

__global__ void fill_kernel(const int* __restrict__ src, const int* __restrict__ dst,
                            const float* __restrict__ dis, int* __restrict__ cursor,
                            int2* __restrict__ edge, int E) {
    int i = blockIdx.x * blockDim.x + threadIdx.x;
    if (i < E) {
        int d = dst[i], s = src[i];
        int pos = atomicAdd(&cursor[d], 1);
        float w = dis[s] * dis[d];
        edge[pos] = make_int2(s, __float_as_int(w));
    }
}

// ---------------- fused GEMM: C[N, OUT] = A[N,KD] @ [W_0|...|W_{NK-1}|Ws] ----------------
// W layout [NK, KD, CPK]; skip (optional) appended as last CPK columns.
// bias0 added only to k==0 block; biasS to skip block.
template<int KD, int CPK, int NK, bool HAS_SKIP>
__global__ __launch_bounds__(256)
void gemm_fused(const float* __restrict__ A, const float* __restrict__ W,
                const float* __restrict__ Ws, const float* __restrict__ bias0,
                const float* __restrict__ biasS, float* __restrict__ C, int N) {
    constexpr int OUT = NK * CPK + (HAS_SKIP ? CPK : 0);
    constexpr int BM = 128, BN = 64, BK = 32;
    __shared__ float As[BK][BM + 4];
    __shared__ float Bs[BK][BN];
    int br = blockIdx.x * BM;
    int colbase = blockIdx.y * BN;
    int tx = threadIdx.x & 15, ty = threadIdx.x >> 4;
    float acc[8][4];
    #pragma unroll
    for (int i = 0; i < 8; i++)
        #pragma unroll
        for (int j = 0; j < 4; j++) acc[i][j] = 0.f;

    for (int k0 = 0; k0 < KD; k0 += BK) {
        // A tile: 128x32 as 1024 float4, transposed into As
        #pragma unroll
        for (int i = 0; i < 4; i++) {
            int fidx = threadIdx.x + 256 * i;
            int r = fidx >> 3, c4 = (fidx & 7) * 4;
            int gr = br + r;
            float4 v = make_float4(0.f, 0.f, 0.f, 0.f);
            if (gr < N) v = *(const float4*)(A + (size_t)gr * KD + k0 + c4);
            As[c4 + 0][r] = v.x; As[c4 + 1][r] = v.y;
            As[c4 + 2][r] = v.z; As[c4 + 3][r] = v.w;
        }
        // B tile: 32x64, gathered from k-major weight layout
        #pragma unroll
        for (int i = 0; i < 8; i++) {
            int idx = threadIdx.x + 256 * i;
            int r = idx >> 6, c = idx & 63;
            int cg = colbase + c;
            int k = cg / CPK, cc = cg % CPK;
            float v;
            if (HAS_SKIP && k == NK)
                v = __ldg(Ws + (size_t)(k0 + r) * CPK + cc);
            else
                v = __ldg(W + (size_t)k * KD * CPK + (size_t)(k0 + r) * CPK + cc);
            Bs[r][c] = v;
        }
        __syncthreads();
        #pragma unroll
        for (int kk = 0; kk < BK; kk++) {
            float4 a0 = *(const float4*)&As[kk][ty * 8];
            float4 a1 = *(const float4*)&As[kk][ty * 8 + 4];
            float4 bv = *(const float4*)&Bs[kk][tx * 4];
            float a[8] = {a0.x, a0.y, a0.z, a0.w, a1.x, a1.y, a1.z, a1.w};
            float b[4] = {bv.x, bv.y, bv.z, bv.w};
            #pragma unroll
            for (int i = 0; i < 8; i++)
                #pragma unroll
                for (int j = 0; j < 4; j++)
                    acc[i][j] = fmaf(a[i], b[j], acc[i][j]);
        }
        __syncthreads();
    }
    // epilogue: add per-column bias, store float4
    int cg0 = colbase + tx * 4;
    float bia[4];
    #pragma unroll
    for (int j = 0; j < 4; j++) {
        int cg = cg0 + j;
        int k = cg / CPK, cc = cg % CPK;
        float v = 0.f;
        if (k == 0) v = __ldg(bias0 + cc);
        else if (HAS_SKIP && k == NK) v = __ldg(biasS + cc);
        bia[j] = v;
    }
    #pragma unroll
    for (int i = 0; i < 8; i++) {
        int gr = br + ty * 8 + i;
        if (gr >= N) continue;
        float4 v = make_float4(acc[i][0] + bia[0], acc[i][1] + bia[1],
                               acc[i][2] + bia[2], acc[i][3] + bia[3]);
        *(float4*)(C + (size_t)gr * OUT + cg0) = v;
    }
}

// ---------------- Clenshaw propagation step ----------------
// out[i,:] = relu?( scale * sum_e w_e * tin[src_e,:] + add[i,:] - sub[i,:] ) + skip[i,:]
// F floats per row; L = F/2 lanes per node (float2 each).
template<int F>
__global__ __launch_bounds__(256)
void clenshaw_prop(const int* __restrict__ rowptr, const int2* __restrict__ edge,
                   const float* __restrict__ tin, int tin_stride,
                   const float* __restrict__ add, int add_stride,
                   const float* __restrict__ sub, int sub_stride,
                   const float* __restrict__ skip, int skip_stride,
                   float* __restrict__ out, int out_stride,
                   float scale, int do_relu, int n) {
    constexpr int L = F / 2;
    int gt = blockIdx.x * blockDim.x + threadIdx.x;
    int node = gt / L;
    if (node >= n) return;
    int sl = gt & (L - 1);
    int beg = __ldg(rowptr + node), end = __ldg(rowptr + node + 1);
    float2 a0 = make_float2(0.f, 0.f), a1 = make_float2(0.f, 0.f);
    int p = beg;
    for (; p + 2 <= end; p += 2) {
        int2 e0 = __ldg(edge + p);
        int2 e1 = __ldg(edge + p + 1);
        float2 t0 = __ldg((const float2*)(tin + (size_t)e0.x * tin_stride) + sl);
        float2 t1 = __ldg((const float2*)(tin + (size_t)e1.x * tin_stride) + sl);
        float w0 = __int_as_float(e0.y), w1 = __int_as_float(e1.y);
        a0.x = fmaf(w0, t0.x, a0.x); a0.y = fmaf(w0, t0.y, a0.y);
        a1.x = fmaf(w1, t1.x, a1.x); a1.y = fmaf(w1, t1.y, a1.y);
    }
    if (p < end) {
        int2 e = __ldg(edge + p);
        float2 t = __ldg((const float2*)(tin + (size_t)e.x * tin_stride) + sl);
        float w = __int_as_float(e.y);
        a0.x = fmaf(w, t.x, a0.x); a0.y = fmaf(w, t.y, a0.y);
    }
    float vx = scale * (a0.x + a1.x);
    float vy = scale * (a0.y + a1.y);
    float2 ad = ((const float2*)(add + (size_t)node * add_stride))[sl];
    vx += ad.x; vy += ad.y;
    if (sub) {
        float2 s = ((const float2*)(sub + (size_t)node * sub_stride))[sl];
        vx -= s.x; vy -= s.y;
    }
    if (do_relu) { vx = fmaxf(vx, 0.f); vy = fmaxf(vy, 0.f); }
    if (skip) {
        float2 s = ((const float2*)(skip + (size_t)node * skip_stride))[sl];
        vx += s.x; vy += s.y;
    }
    ((float2*)(out + (size_t)node * out_stride))[sl] = make_float2(vx, vy);
}

// ---------------- concat [h | x] -> cat (float4 granularity) ----------------
__global__ void concat_kernel(const float* __restrict__ h, const float* __restrict__ x,
                              float* __restrict__ cat, int N) {
    int i = blockIdx.x * blockDim.x + threadIdx.x;
    int total = N * 48;   // 192 floats = 48 float4 per node
    if (i >= total) return;
    int node = i / 48, j = i % 48;
    float4 v;
    if (j < 16) v = ((const float4*)h)[(size_t)node * 16 + j];
    else        v = ((const float4*)x)[(size_t)node * 32 + (j - 16)];
    ((float4*)cat)[i] = v;
}

// ---------------- host orchestration ----------------
static void prop64(const int* rowptr, const int2* edge,
                   const float* tin, int ts, const float* add, int as,
                   const float* sub, int ss, const float* skip, int ks,
                   float* out, int os, float scale, int relu) {
    int blocks = (NN * 32 + 255) / 256;
    clenshaw_prop<64><<<blocks, 256>>>(rowptr, edge, tin, ts, add, as, sub, ss,
                                       skip, ks, out, os, scale, relu, NN);
}

static void cheb_layer(const float* h, int kd,
                       const float* W, const float* b,
                       const float* Ws, const float* bs,
                       float* hout, const int* rowptr, const int2* edge,
                       float* C, float* B0, float* B1, float* B2) {
    dim3 grid((NN + 127) / 128, 7);
    if (kd == 128) gemm_fused<128, 64, 6, true><<<grid, 256>>>(h, W, Ws, b, bs, C, NN);
    else           gemm_fused<64,  64, 6, true><<<grid, 256>>>(h, W, Ws, b, bs, C, NN);
    // Clenshaw: b5 = c5 (in C, stride 448)
    // b4 = c4 + 2L b5
    prop64(rowptr, edge, C + 5 * 64, 448, C + 4 * 64, 448, nullptr, 0,
           nullptr, 0, B0, 64, -2.f, 0);
    // b3 = c3 + 2L b4 - b5
    prop64(rowptr, edge, B0, 64, C + 3 * 64, 448, C + 5 * 64, 448,
           nullptr, 0, B1, 64, -2.f, 0);
    // b2 = c2 + 2L b3 - b4
    prop64(rowptr, edge, B1, 64, C + 2 * 64, 448, B0, 64,
           nullptr, 0, B2, 64, -2.f, 0);
    // b1 = c1 + 2L b2 - b3
    prop64(rowptr, edge, B2, 64, C + 1 * 64, 448, B1, 64,
           nullptr, 0, B0, 64, -2.f, 0);
    // h = relu(c0 + L b1 - b2) + skip
    prop64(rowptr, edge, B0, 64, C, 448, B2, 64,
           C + 6 * 64, 448, hout, 64, -1.f, 1);
}

extern "C" void kernel_launch(void* const* d_in, const int* in_sizes, int n_in,
                              void* d_out, int out_size) {
    const float* x   = (const float*)d_in[0];
    const int*   ei  = (const int*)d_in[1];
    const float* W0  = (const float*)d_in[2];
    const float* b0  = (const float*)d_in[3];
    const float* Ws0 = (const float*)d_in[4];
    const float* bs0 = (const float*)d_in[5];
    const float* W1  = (const float*)d_in[6];
    const float* b1  = (const float*)d_in[7];
    const float* Ws1 = (const float*)d_in[8];
    const float* bs1 = (const float*)d_in[9];
    const float* W2  = (const float*)d_in[10];
    const float* b2  = (const float*)d_in[11];
    const float* Ws2 = (const float*)d_in[12];
    const float* bs2 = (const float*)d_in[13];
    const float* Wm  = (const float*)d_in[14];
    const float* bm  = (const float*)d_in[15];
    float* out = (float*)d_out;

    const int* src = ei;
    const int* dst = ei + NE;

    void* p;
    cudaGetSymbolAddress(&p, g_cnt);    int*   cnt    = (int*)p;
    cudaGetSymbolAddress(&p, g_rowptr); int*   rowptr = (int*)p;
    cudaGetSymbolAddress(&p, g_cursor); int*   cursor = (int*)p;
    cudaGetSymbolAddress(&p, g_dis);    float* dis    = (float*)p;
    cudaGetSymbolAddress(&p, g_edge);   int2*  edge   = (int2*)p;
    cudaGetSymbolAddress(&p, g_C);      float* C      = (float*)p;
    cudaGetSymbolAddress(&p, g_b0);     float* B0     = (float*)p;
    cudaGetSymbolAddress(&p, g_b1);     float* B1     = (float*)p;
    cudaGetSymbolAddress(&p, g_b2);     float* B2     = (float*)p;
    cudaGetSymbolAddress(&p, g_cat);    float* cat    = (float*)p;
    cudaGetSymbolAddress(&p, g_h1);     float* h1     = (float*)p;
    cudaGetSymbolAddress(&p, g_h2);     float* h2     = (float*)p;

    // ---- preprocessing: degree, norm weights, CSR (sorted by dst) ----
    cudaMemsetAsync(cnt, 0, NN * sizeof(int), 0);
    hist_kernel<<<(NE + 255) / 256, 256>>>(dst, cnt, NE);
    dis_kernel<<<(NN + 255) / 256, 256>>>(cnt, dis, NN);
    scan_kernel<<<1, 1024>>>(cnt, rowptr, cursor, NN);
    fill_kernel<<<(NE + 255) / 256, 256>>>(src, dst, dis, cursor, edge, NE);

    // ---- 3 Kipf blocks (Clenshaw evaluation) ----
    cheb_layer(x,  128, W0, b0, Ws0, bs0, h1, rowptr, edge, C, B0, B1, B2);
    cheb_layer(h1,  64, W1, b1, Ws1, bs1, h2, rowptr, edge, C, B0, B1, B2);
    cheb_layer(h2,  64, W2, b2, Ws2, bs2, h1, rowptr, edge, C, B0, B1, B2);

    // ---- mix head: concat(h, x) -> ChebConv K=2 -> out ----
    concat_kernel<<<(NN * 48 + 255) / 256, 256>>>(h1, x, cat, NN);
    {
        dim3 grid((NN + 127) / 128, 1);
        // Cmix[N,64] = cat @ [Wm0 | Wm1]; bias bm on c0 block only
        gemm_fused<192, 32, 2, false><<<grid, 256>>>(cat, Wm, nullptr, bm, nullptr, B0, NN);
        // out = c0 + L c1
        int blocks = (NN * 16 + 255) / 256;
        clenshaw_prop<32><<<blocks, 256>>>(rowptr, edge, B0 + 32, 64, B0, 64,
                                           nullptr, 0, nullptr, 0, out, 32, -1.f, NN > 0 ? 0 : 0, NN);
    }
}

// round 4
// speedup vs baseline: 1.5356x; 1.1966x over previous
#include <cuda_runtime.h>
#include <cstdint>

#define NN 100000
#define NE 3200000
#define NH 64

// ---------------- scratch (__device__ globals: allocation-free) ----------------
__device__ int   g_cnt[NN];
__device__ int   g_partial[512];
__device__ int   g_rowptr[NN + 1];
__device__ int   g_cursor[NN];
__device__ float g_dis[NN];
__device__ int2  g_edge[NE];            // .x = src node, .y = bit-cast edge weight
__device__ float g_C[(size_t)NN * 448]; // fused GEMM output: c_0..c_5 | skip
__device__ float g_b0[NN * NH];
__device__ float g_b1[NN * NH];
__device__ float g_b2[NN * NH];
__device__ float g_cat[NN * 192];
__device__ float g_h1[NN * NH];
__device__ float g_h2[NN * NH];
// tf32 transposed weights (rows = output col, contiguous K) + fused bias vectors
__device__ float g_Wt0[448 * 128];
__device__ float g_Wt1[448 * 64];
__device__ float g_Wt2[448 * 64];
__device__ float g_Wtm[64 * 192];
__device__ float g_bias0[448];
__device__ float g_bias1[448];
__device__ float g_bias2[448];
__device__ float g_biasm[64];

__device__ __forceinline__ float to_tf32(float v) {
    uint32_t u;
    asm("cvt.rna.tf32.f32 %0, %1;" : "=r"(u) : "f"(v));
    return __uint_as_float(u);
}

__device__ __forceinline__ void mma_m16n8k8(float* c, uint32_t a0, uint32_t a1,
                                            uint32_t a2, uint32_t a3,
                                            uint32_t b0, uint32_t b1) {
    asm volatile(
        "mma.sync.aligned.m16n8k8.row.col.f32.tf32.tf32.f32 "
        "{%0,%1,%2,%3}, {%4,%5,%6,%7}, {%8,%9}, {%0,%1,%2,%3};"
        : "+f"(c[0]), "+f"(c[1]), "+f"(c[2]), "+f"(c[3])
        : "r"(a0), "r"(a1), "r"(a2), "r"(a3), "r"(b0), "r"(b1));
}

// ---------------- graph preprocessing ----------------
__global__ void hist_kernel(const int* __restrict__ dst, int* __restrict__ cnt, int E) {
    int i = blockIdx.x * blockDim.x + threadIdx.x;
    if (i < E) atomicAdd(&cnt[dst[i]], 1);
}

__global__ void dis_kernel(const int* __restrict__ cnt, float* __restrict__ dis, int n) {
    int i = blockIdx.x * blockDim.x + threadIdx.x;
    if (i < n) dis[i] = cnt[i] > 0 ? rsqrtf((float)cnt[i]) : 0.0f;
}

__global__ void reduce_kernel(const int* __restrict__ cnt, int* __restrict__ partial, int n) {
    __shared__ int s[8];
    int i = blockIdx.x * 256 + threadIdx.x;
    int v = (i < n) ? cnt[i] : 0;
    #pragma unroll
    for (int o = 16; o; o >>= 1) v += __shfl_down_sync(0xffffffffu, v, o);
    if ((threadIdx.x & 31) == 0) s[threadIdx.x >> 5] = v;
    __syncthreads();
    if (threadIdx.x < 8) {
        int t = s[threadIdx.x];
        #pragma unroll
        for (int o = 4; o; o >>= 1) t += __shfl_down_sync(0xffu, t, o);
        if (threadIdx.x == 0) partial[blockIdx.x] = t;
    }
}

__global__ void scanp_kernel(int* __restrict__ partial, int nb, int* __restrict__ total_out) {
    __shared__ int ws[16];
    int tid = threadIdx.x, lane = tid & 31, w = tid >> 5;
    int v = (tid < nb) ? partial[tid] : 0;
    int x = v;
    #pragma unroll
    for (int o = 1; o < 32; o <<= 1) {
        int y = __shfl_up_sync(0xffffffffu, x, o);
        if (lane >= o) x += y;
    }
    if (lane == 31) ws[w] = x;
    __syncthreads();
    if (w == 0 && lane < 16) {
        int t = ws[lane];
        #pragma unroll
        for (int o = 1; o < 16; o <<= 1) {
            int y = __shfl_up_sync(0xffffu, t, o);
            if (lane >= o) t += y;
        }
        ws[lane] = t;
    }
    __syncthreads();
    int excl = x - v + (w ? ws[w - 1] : 0);
    if (tid < nb) partial[tid] = excl;
    if (tid == nb - 1) total_out[0] = excl + v;
}

__global__ void apply_kernel(const int* __restrict__ cnt, const int* __restrict__ partial,
                             int* __restrict__ rowptr, int* __restrict__ cursor, int n) {
    __shared__ int ws[8];
    int i = blockIdx.x * 256 + threadIdx.x;
    int lane = threadIdx.x & 31, w = threadIdx.x >> 5;
    int v = (i < n) ? cnt[i] : 0;
    int x = v;
    #pragma unroll
    for (int o = 1; o < 32; o <<= 1) {
        int y = __shfl_up_sync(0xffffffffu, x, o);
        if (lane >= o) x += y;
    }
    if (lane == 31) ws[w] = x;
    __syncthreads();
    if (w == 0 && lane < 8) {
        int t = ws[lane];
        #pragma unroll
        for (int o = 1; o < 8; o <<= 1) {
            int y = __shfl_up_sync(0xffu, t, o);
            if (lane >= o) t += y;
        }
        ws[lane] = t;
    }
    __syncthreads();
    int excl = x - v + (w ? ws[w - 1] : 0) + partial[blockIdx.x];
    if (i < n) { rowptr[i] = excl; cursor[i] = excl; }
}

__global__ void fill_kernel(const int* __restrict__ src, const int* __restrict__ dst,
                            const float* __restrict__ dis, int* __restrict__ cursor,
                            int2* __restrict__ edge, int E) {
    int i = blockIdx.x * blockDim.x + threadIdx.x;
    if (i < E) {
        int d = dst[i], s = src[i];
        int pos = atomicAdd(&cursor[d], 1);
        float w = dis[s] * dis[d];
        edge[pos] = make_int2(s, __float_as_int(w));
    }
}

// ---------------- weight prep: transpose to [OUT][KD], cvt to tf32; fused biases ----------------
__global__ void prep_weights(const float* __restrict__ W0, const float* __restrict__ Ws0,
                             const float* __restrict__ W1, const float* __restrict__ Ws1,
                             const float* __restrict__ W2, const float* __restrict__ Ws2,
                             const float* __restrict__ Wm,
                             const float* __restrict__ b0, const float* __restrict__ bs0,
                             const float* __restrict__ b1, const float* __restrict__ bs1,
                             const float* __restrict__ b2, const float* __restrict__ bs2,
                             const float* __restrict__ bm,
                             float* __restrict__ Wt0, float* __restrict__ Wt1,
                             float* __restrict__ Wt2, float* __restrict__ Wtm,
                             float* __restrict__ bias0, float* __restrict__ bias1,
                             float* __restrict__ bias2, float* __restrict__ biasm) {
    int idx = blockIdx.x * blockDim.x + threadIdx.x;
    const int S0 = 448 * 128, S1 = 448 * 64, S2 = 448 * 64, SM = 64 * 192;
    if (idx < S0) {
        int n = idx / 128, k = idx % 128;
        float v = (n < 384) ? W0[(size_t)(n / 64) * 128 * 64 + (size_t)k * 64 + (n % 64)]
                            : Ws0[(size_t)k * 64 + (n - 384)];
        Wt0[idx] = to_tf32(v);
        return;
    }
    idx -= S0;
    if (idx < S1) {
        int n = idx / 64, k = idx % 64;
        float v = (n < 384) ? W1[(size_t)(n / 64) * 64 * 64 + (size_t)k * 64 + (n % 64)]
                            : Ws1[(size_t)k * 64 + (n - 384)];
        Wt1[idx] = to_tf32(v);
        return;
    }
    idx -= S1;
    if (idx < S2) {
        int n = idx / 64, k = idx % 64;
        float v = (n < 384) ? W2[(size_t)(n / 64) * 64 * 64 + (size_t)k * 64 + (n % 64)]
                            : Ws2[(size_t)k * 64 + (n - 384)];
        Wt2[idx] = to_tf32(v);
        return;
    }
    idx -= S2;
    if (idx < SM) {
        int n = idx / 192, k = idx % 192;
        float v = (n < 32) ? Wm[(size_t)k * 32 + n]
                           : Wm[(size_t)192 * 32 + (size_t)k * 32 + (n - 32)];
        Wtm[idx] = to_tf32(v);
        return;
    }
    idx -= SM;
    if (idx < 448) { bias0[idx] = (idx < 64) ? b0[idx] : (idx >= 384 ? bs0[idx - 384] : 0.f); return; }
    idx -= 448;
    if (idx < 448) { bias1[idx] = (idx < 64) ? b1[idx] : (idx >= 384 ? bs1[idx - 384] : 0.f); return; }
    idx -= 448;
    if (idx < 448) { bias2[idx] = (idx < 64) ? b2[idx] : (idx >= 384 ? bs2[idx - 384] : 0.f); return; }
    idx -= 448;
    if (idx < 64) { biasm[idx] = (idx < 32) ? bm[idx] : 0.f; return; }
}

// ---------------- mma.sync tf32 GEMM ----------------
// C[br+0:128, colbase:colbase+64] = A[., 0:KD] @ Wt^T (+ bias[col])
// 256 threads = 8 warps (4 m x 2 n); warp tile 32x32; m16n8k8 fragments.
// As[m][k] stride 36 (fragment LDS conflict-free: bank = 4*row + k).
template<int KD>
__global__ __launch_bounds__(256)
void gemm_mma(const float* __restrict__ A, const float* __restrict__ Wt,
              const float* __restrict__ biasfull, float* __restrict__ C,
              int OUT, int N) {
    constexpr int BM = 128, BN = 64, BK = 32, LDA = 36;
    __shared__ float As[BM * LDA];
    __shared__ float Bs[BN * LDA];
    const uint32_t* Asu = (const uint32_t*)As;
    const uint32_t* Bsu = (const uint32_t*)Bs;

    int tid = threadIdx.x;
    int lane = tid & 31, wid = tid >> 5;
    int wm = wid & 3, wn = wid >> 2;          // 4 x 2 warp grid
    int quad = lane >> 2, qt = lane & 3;      // groupID, threadID_in_group
    int br = blockIdx.x * BM;
    int colbase = blockIdx.y * BN;

    float acc[2][4][4];
    #pragma unroll
    for (int mi = 0; mi < 2; mi++)
        #pragma unroll
        for (int ni = 0; ni < 4; ni++)
            #pragma unroll
            for (int j = 0; j < 4; j++) acc[mi][ni][j] = 0.f;

    for (int k0 = 0; k0 < KD; k0 += BK) {
        // A tile: 128x32 floats = 1024 float4; cvt to tf32
        #pragma unroll
        for (int t = 0; t < 4; t++) {
            int i4 = tid + 256 * t;
            int r = i4 >> 3, c4 = i4 & 7;
            int gr = br + r;
            float4 v = make_float4(0.f, 0.f, 0.f, 0.f);
            if (gr < N) v = *(const float4*)(A + (size_t)gr * KD + k0 + c4 * 4);
            v.x = to_tf32(v.x); v.y = to_tf32(v.y); v.z = to_tf32(v.z); v.w = to_tf32(v.w);
            *(float4*)(As + r * LDA + c4 * 4) = v;
        }
        // B tile: 64x32 floats = 512 float4 (already tf32)
        #pragma unroll
        for (int t = 0; t < 2; t++) {
            int i4 = tid + 256 * t;
            int n = i4 >> 3, c4 = i4 & 7;
            float4 v = *(const float4*)(Wt + (size_t)(colbase + n) * KD + k0 + c4 * 4);
            *(float4*)(Bs + n * LDA + c4 * 4) = v;
        }
        __syncthreads();
        #pragma unroll
        for (int ks = 0; ks < 4; ks++) {
            int kk = ks * 8;
            uint32_t a[2][4];
            #pragma unroll
            for (int mi = 0; mi < 2; mi++) {
                int row = wm * 32 + mi * 16 + quad;
                a[mi][0] = Asu[row * LDA + kk + qt];
                a[mi][1] = Asu[(row + 8) * LDA + kk + qt];
                a[mi][2] = Asu[row * LDA + kk + qt + 4];
                a[mi][3] = Asu[(row + 8) * LDA + kk + qt + 4];
            }
            #pragma unroll
            for (int ni = 0; ni < 4; ni++) {
                int col = wn * 32 + ni * 8 + quad;
                uint32_t b0 = Bsu[col * LDA + kk + qt];
                uint32_t b1 = Bsu[col * LDA + kk + qt + 4];
                #pragma unroll
                for (int mi = 0; mi < 2; mi++)
                    mma_m16n8k8(acc[mi][ni], a[mi][0], a[mi][1], a[mi][2], a[mi][3], b0, b1);
            }
        }
        __syncthreads();
    }
    // epilogue: bias + store (c0,c1 -> row; c2,c3 -> row+8), float2 stores
    #pragma unroll
    for (int mi = 0; mi < 2; mi++) {
        int r0 = br + wm * 32 + mi * 16 + quad;
        #pragma unroll
        for (int ni = 0; ni < 4; ni++) {
            int cg = colbase + wn * 32 + ni * 8 + qt * 2;
            float bx = __ldg(biasfull + cg), by = __ldg(biasfull + cg + 1);
            if (r0 < N)
                *(float2*)(C + (size_t)r0 * OUT + cg) =
                    make_float2(acc[mi][ni][0] + bx, acc[mi][ni][1] + by);
            if (r0 + 8 < N)
                *(float2*)(C + (size_t)(r0 + 8) * OUT + cg) =
                    make_float2(acc[mi][ni][2] + bx, acc[mi][ni][3] + by);
        }
    }
}

// ---------------- Clenshaw propagation step ----------------
template<int F>
__global__ __launch_bounds__(256)
void clenshaw_prop(const int* __restrict__ rowptr, const int2* __restrict__ edge,
                   const float* __restrict__ tin, int tin_stride,
                   const float* __restrict__ add, int add_stride,
                   const float* __restrict__ sub, int sub_stride,
                   const float* __restrict__ skip, int skip_stride,
                   float* __restrict__ out, int out_stride,
                   float scale, int do_relu, int n) {
    constexpr int L = F / 2;
    int gt = blockIdx.x * blockDim.x + threadIdx.x;
    int node = gt / L;
    if (node >= n) return;
    int sl = gt & (L - 1);
    int beg = __ldg(rowptr + node), end = __ldg(rowptr + node + 1);
    float2 a0 = make_float2(0.f, 0.f), a1 = make_float2(0.f, 0.f);
    int p = beg;
    for (; p + 2 <= end; p += 2) {
        int2 e0 = __ldg(edge + p);
        int2 e1 = __ldg(edge + p + 1);
        float2 t0 = __ldg((const float2*)(tin + (size_t)e0.x * tin_stride) + sl);
        float2 t1 = __ldg((const float2*)(tin + (size_t)e1.x * tin_stride) + sl);
        float w0 = __int_as_float(e0.y), w1 = __int_as_float(e1.y);
        a0.x = fmaf(w0, t0.x, a0.x); a0.y = fmaf(w0, t0.y, a0.y);
        a1.x = fmaf(w1, t1.x, a1.x); a1.y = fmaf(w1, t1.y, a1.y);
    }
    if (p < end) {
        int2 e = __ldg(edge + p);
        float2 t = __ldg((const float2*)(tin + (size_t)e.x * tin_stride) + sl);
        float w = __int_as_float(e.y);
        a0.x = fmaf(w, t.x, a0.x); a0.y = fmaf(w, t.y, a0.y);
    }
    float vx = scale * (a0.x + a1.x);
    float vy = scale * (a0.y + a1.y);
    float2 ad = ((const float2*)(add + (size_t)node * add_stride))[sl];
    vx += ad.x; vy += ad.y;
    if (sub) {
        float2 s = ((const float2*)(sub + (size_t)node * sub_stride))[sl];
        vx -= s.x; vy -= s.y;
    }
    if (do_relu) { vx = fmaxf(vx, 0.f); vy = fmaxf(vy, 0.f); }
    if (skip) {
        float2 s = ((const float2*)(skip + (size_t)node * skip_stride))[sl];
        vx += s.x; vy += s.y;
    }
    ((float2*)(out + (size_t)node * out_stride))[sl] = make_float2(vx, vy);
}

// ---------------- concat [h | x] ----------------
__global__ void concat_kernel(const float* __restrict__ h, const float* __restrict__ x,
                              float* __restrict__ cat, int N) {
    int i = blockIdx.x * blockDim.x + threadIdx.x;
    int total = N * 48;
    if (i >= total) return;
    int node = i / 48, j = i % 48;
    float4 v;
    if (j < 16) v = ((const float4*)h)[(size_t)node * 16 + j];
    else        v = ((const float4*)x)[(size_t)node * 32 + (j - 16)];
    ((float4*)cat)[i] = v;
}

// ---------------- host orchestration ----------------
static void prop64(const int* rowptr, const int2* edge,
                   const float* tin, int ts, const float* add, int as,
                   const float* sub, int ss, const float* skip, int ks,
                   float* out, int os, float scale, int relu) {
    int blocks = (NN * 32 + 255) / 256;
    clenshaw_prop<64><<<blocks, 256>>>(rowptr, edge, tin, ts, add, as, sub, ss,
                                       skip, ks, out, os, scale, relu, NN);
}

static void cheb_layer(const float* h, int kd,
                       const float* Wt, const float* biasfull,
                       float* hout, const int* rowptr, const int2* edge,
                       float* C, float* B0, float* B1, float* B2) {
    dim3 grid((NN + 127) / 128, 7);
    if (kd == 128) gemm_mma<128><<<grid, 256>>>(h, Wt, biasfull, C, 448, NN);
    else           gemm_mma<64><<<grid, 256>>>(h, Wt, biasfull, C, 448, NN);
    // Clenshaw recursion (b5 = c5 lives in C, stride 448)
    prop64(rowptr, edge, C + 5 * 64, 448, C + 4 * 64, 448, nullptr, 0,
           nullptr, 0, B0, 64, -2.f, 0);                                       // b4
    prop64(rowptr, edge, B0, 64, C + 3 * 64, 448, C + 5 * 64, 448,
           nullptr, 0, B1, 64, -2.f, 0);                                       // b3
    prop64(rowptr, edge, B1, 64, C + 2 * 64, 448, B0, 64,
           nullptr, 0, B2, 64, -2.f, 0);                                       // b2
    prop64(rowptr, edge, B2, 64, C + 1 * 64, 448, B1, 64,
           nullptr, 0, B0, 64, -2.f, 0);                                       // b1
    prop64(rowptr, edge, B0, 64, C, 448, B2, 64,
           C + 6 * 64, 448, hout, 64, -1.f, 1);                                // out
}

extern "C" void kernel_launch(void* const* d_in, const int* in_sizes, int n_in,
                              void* d_out, int out_size) {
    const float* x   = (const float*)d_in[0];
    const int*   ei  = (const int*)d_in[1];
    const float* W0  = (const float*)d_in[2];
    const float* b0  = (const float*)d_in[3];
    const float* Ws0 = (const float*)d_in[4];
    const float* bs0 = (const float*)d_in[5];
    const float* W1  = (const float*)d_in[6];
    const float* b1  = (const float*)d_in[7];
    const float* Ws1 = (const float*)d_in[8];
    const float* bs1 = (const float*)d_in[9];
    const float* W2  = (const float*)d_in[10];
    const float* b2  = (const float*)d_in[11];
    const float* Ws2 = (const float*)d_in[12];
    const float* bs2 = (const float*)d_in[13];
    const float* Wm  = (const float*)d_in[14];
    const float* bm  = (const float*)d_in[15];
    float* out = (float*)d_out;

    const int* src = ei;
    const int* dst = ei + NE;

    void* p;
    cudaGetSymbolAddress(&p, g_cnt);     int*   cnt     = (int*)p;
    cudaGetSymbolAddress(&p, g_partial); int*   partial = (int*)p;
    cudaGetSymbolAddress(&p, g_rowptr);  int*   rowptr  = (int*)p;
    cudaGetSymbolAddress(&p, g_cursor);  int*   cursor  = (int*)p;
    cudaGetSymbolAddress(&p, g_dis);     float* dis     = (float*)p;
    cudaGetSymbolAddress(&p, g_edge);    int2*  edge    = (int2*)p;
    cudaGetSymbolAddress(&p, g_C);       float* C       = (float*)p;
    cudaGetSymbolAddress(&p, g_b0);      float* B0      = (float*)p;
    cudaGetSymbolAddress(&p, g_b1);      float* B1      = (float*)p;
    cudaGetSymbolAddress(&p, g_b2);      float* B2      = (float*)p;
    cudaGetSymbolAddress(&p, g_cat);     float* cat     = (float*)p;
    cudaGetSymbolAddress(&p, g_h1);      float* h1      = (float*)p;
    cudaGetSymbolAddress(&p, g_h2);      float* h2      = (float*)p;
    cudaGetSymbolAddress(&p, g_Wt0);     float* Wt0     = (float*)p;
    cudaGetSymbolAddress(&p, g_Wt1);     float* Wt1     = (float*)p;
    cudaGetSymbolAddress(&p, g_Wt2);     float* Wt2     = (float*)p;
    cudaGetSymbolAddress(&p, g_Wtm);     float* Wtm     = (float*)p;
    cudaGetSymbolAddress(&p, g_bias0);   float* bias0   = (float*)p;
    cudaGetSymbolAddress(&p, g_bias1);   float* bias1   = (float*)p;
    cudaGetSymbolAddress(&p, g_bias2);   float* bias2   = (float*)p;
    cudaGetSymbolAddress(&p, g_biasm);   float* biasm   = (float*)p;

    // ---- weight prep (independent of graph) ----
    {
        int total = 448 * 128 + 448 * 64 + 448 * 64 + 64 * 192 + 448 * 3 + 64;
        prep_weights<<<(total + 255) / 256, 256>>>(W0, Ws0, W1, Ws1, W2, Ws2, Wm,
                                                   b0, bs0, b1, bs1, b2, bs2, bm,
                                                   Wt0, Wt1, Wt2, Wtm,
                                                   bias0, bias1, bias2, biasm);
    }

    // ---- preprocessing: degree, norm weights, CSR (sorted by dst) ----
    cudaMemsetAsync(cnt, 0, NN * sizeof(int), 0);
    hist_kernel<<<(NE + 255) / 256, 256>>>(dst, cnt, NE);
    dis_kernel<<<(NN + 255) / 256, 256>>>(cnt, dis, NN);
    int nb = (NN + 255) / 256;
    reduce_kernel<<<nb, 256>>>(cnt, partial, NN);
    scanp_kernel<<<1, 512>>>(partial, nb, rowptr + NN);
    apply_kernel<<<nb, 256>>>(cnt, partial, rowptr, cursor, NN);
    fill_kernel<<<(NE + 255) / 256, 256>>>(src, dst, dis, cursor, edge, NE);

    // ---- 3 Kipf blocks (Clenshaw) ----
    cheb_layer(x,  128, Wt0, bias0, h1, rowptr, edge, C, B0, B1, B2);
    cheb_layer(h1,  64, Wt1, bias1, h2, rowptr, edge, C, B0, B1, B2);
    cheb_layer(h2,  64, Wt2, bias2, h1, rowptr, edge, C, B0, B1, B2);

    // ---- mix head: concat(h, x) -> ChebConv K=2 -> out ----
    concat_kernel<<<(NN * 48 + 255) / 256, 256>>>(h1, x, cat, NN);
    {
        dim3 grid((NN + 127) / 128, 1);
        gemm_mma<192><<<grid, 256>>>(cat, Wtm, biasm, B0, 64, NN);
        int blocks = (NN * 16 + 255) / 256;
        clenshaw_prop<32><<<blocks, 256>>>(rowptr, edge, B0 + 32, 64, B0, 64,
                                           nullptr, 0, nullptr, 0, out, 32, -1.f, 0, NN);
    }
}

// round 5
// speedup vs baseline: 1.8975x; 1.2357x over previous
#include <cuda_runtime.h>
#include <cuda_fp16.h>
#include <cstdint>

#define NN 100000
#define NE 3200000
#define NH 64

// ---------------- scratch (__device__ globals: allocation-free) ----------------
__device__ int    g_cnt[NN];
__device__ int    g_partial[512];
__device__ int    g_rowptr[NN + 1];
__device__ int    g_cursor[NN];
__device__ float  g_dis[NN];
__device__ int    g_esrc[NE];             // CSR-by-dst src indices (weights are separable!)
__device__ float  g_C[(size_t)NN * 448];  // fused GEMM output: c_0..c_5 | skip
__device__ float  g_b0[NN * NH];
__device__ float  g_b1[NN * NH];
__device__ float  g_b2[NN * NH];
__device__ __half g_H0[NN * NH];          // pre-scaled (dis⊙) fp16 gather buffers
__device__ __half g_H1[NN * NH];
__device__ __half g_H2[NN * NH];
__device__ __half g_H3[NN * NH];
__device__ float  g_cat[NN * 192];
__device__ float  g_h1[NN * NH];
__device__ float  g_h2[NN * NH];
// tf32 transposed weights (rows = output col, contiguous K) + fused bias vectors
__device__ float g_Wt0[448 * 128];
__device__ float g_Wt1[448 * 64];
__device__ float g_Wt2[448 * 64];
__device__ float g_Wtm[64 * 192];
__device__ float g_bias0[448];
__device__ float g_bias1[448];
__device__ float g_bias2[448];
__device__ float g_biasm[64];

__device__ __forceinline__ float to_tf32(float v) {
    uint32_t u;
    asm("cvt.rna.tf32.f32 %0, %1;" : "=r"(u) : "f"(v));
    return __uint_as_float(u);
}

__device__ __forceinline__ void mma_m16n8k8(float* c, uint32_t a0, uint32_t a1,
                                            uint32_t a2, uint32_t a3,
                                            uint32_t b0, uint32_t b1) {
    asm volatile(
        "mma.sync.aligned.m16n8k8.row.col.f32.tf32.tf32.f32 "
        "{%0,%1,%2,%3}, {%4,%5,%6,%7}, {%8,%9}, {%0,%1,%2,%3};"
        : "+f"(c[0]), "+f"(c[1]), "+f"(c[2]), "+f"(c[3])
        : "r"(a0), "r"(a1), "r"(a2), "r"(a3), "r"(b0), "r"(b1));
}

// ---------------- graph preprocessing ----------------
__global__ void hist_kernel(const int* __restrict__ dst, int* __restrict__ cnt, int E) {
    int i = blockIdx.x * blockDim.x + threadIdx.x;
    if (i < E) atomicAdd(&cnt[dst[i]], 1);
}

__global__ void dis_kernel(const int* __restrict__ cnt, float* __restrict__ dis, int n) {
    int i = blockIdx.x * blockDim.x + threadIdx.x;
    if (i < n) dis[i] = cnt[i] > 0 ? rsqrtf((float)cnt[i]) : 0.0f;
}

__global__ void reduce_kernel(const int* __restrict__ cnt, int* __restrict__ partial, int n) {
    __shared__ int s[8];
    int i = blockIdx.x * 256 + threadIdx.x;
    int v = (i < n) ? cnt[i] : 0;
    #pragma unroll
    for (int o = 16; o; o >>= 1) v += __shfl_down_sync(0xffffffffu, v, o);
    if ((threadIdx.x & 31) == 0) s[threadIdx.x >> 5] = v;
    __syncthreads();
    if (threadIdx.x < 8) {
        int t = s[threadIdx.x];
        #pragma unroll
        for (int o = 4; o; o >>= 1) t += __shfl_down_sync(0xffu, t, o);
        if (threadIdx.x == 0) partial[blockIdx.x] = t;
    }
}

__global__ void scanp_kernel(int* __restrict__ partial, int nb, int* __restrict__ total_out) {
    __shared__ int ws[16];
    int tid = threadIdx.x, lane = tid & 31, w = tid >> 5;
    int v = (tid < nb) ? partial[tid] : 0;
    int x = v;
    #pragma unroll
    for (int o = 1; o < 32; o <<= 1) {
        int y = __shfl_up_sync(0xffffffffu, x, o);
        if (lane >= o) x += y;
    }
    if (lane == 31) ws[w] = x;
    __syncthreads();
    if (w == 0 && lane < 16) {
        int t = ws[lane];
        #pragma unroll
        for (int o = 1; o < 16; o <<= 1) {
            int y = __shfl_up_sync(0xffffu, t, o);
            if (lane >= o) t += y;
        }
        ws[lane] = t;
    }
    __syncthreads();
    int excl = x - v + (w ? ws[w - 1] : 0);
    if (tid < nb) partial[tid] = excl;
    if (tid == nb - 1) total_out[0] = excl + v;
}

__global__ void apply_kernel(const int* __restrict__ cnt, const int* __restrict__ partial,
                             int* __restrict__ rowptr, int* __restrict__ cursor, int n) {
    __shared__ int ws[8];
    int i = blockIdx.x * 256 + threadIdx.x;
    int lane = threadIdx.x & 31, w = threadIdx.x >> 5;
    int v = (i < n) ? cnt[i] : 0;
    int x = v;
    #pragma unroll
    for (int o = 1; o < 32; o <<= 1) {
        int y = __shfl_up_sync(0xffffffffu, x, o);
        if (lane >= o) x += y;
    }
    if (lane == 31) ws[w] = x;
    __syncthreads();
    if (w == 0 && lane < 8) {
        int t = ws[lane];
        #pragma unroll
        for (int o = 1; o < 8; o <<= 1) {
            int y = __shfl_up_sync(0xffu, t, o);
            if (lane >= o) t += y;
        }
        ws[lane] = t;
    }
    __syncthreads();
    int excl = x - v + (w ? ws[w - 1] : 0) + partial[blockIdx.x];
    if (i < n) { rowptr[i] = excl; cursor[i] = excl; }
}

__global__ void fill_kernel(const int* __restrict__ src, const int* __restrict__ dst,
                            int* __restrict__ cursor, int* __restrict__ esrc, int E) {
    int i = blockIdx.x * blockDim.x + threadIdx.x;
    if (i < E) {
        int d = dst[i];
        int pos = atomicAdd(&cursor[d], 1);
        esrc[pos] = src[i];
    }
}

// ---------------- weight prep: transpose to [OUT][KD], cvt to tf32; fused biases ----------------
__global__ void prep_weights(const float* __restrict__ W0, const float* __restrict__ Ws0,
                             const float* __restrict__ W1, const float* __restrict__ Ws1,
                             const float* __restrict__ W2, const float* __restrict__ Ws2,
                             const float* __restrict__ Wm,
                             const float* __restrict__ b0, const float* __restrict__ bs0,
                             const float* __restrict__ b1, const float* __restrict__ bs1,
                             const float* __restrict__ b2, const float* __restrict__ bs2,
                             const float* __restrict__ bm,
                             float* __restrict__ Wt0, float* __restrict__ Wt1,
                             float* __restrict__ Wt2, float* __restrict__ Wtm,
                             float* __restrict__ bias0, float* __restrict__ bias1,
                             float* __restrict__ bias2, float* __restrict__ biasm) {
    int idx = blockIdx.x * blockDim.x + threadIdx.x;
    const int S0 = 448 * 128, S1 = 448 * 64, S2 = 448 * 64, SM = 64 * 192;
    if (idx < S0) {
        int n = idx / 128, k = idx % 128;
        float v = (n < 384) ? W0[(size_t)(n / 64) * 128 * 64 + (size_t)k * 64 + (n % 64)]
                            : Ws0[(size_t)k * 64 + (n - 384)];
        Wt0[idx] = to_tf32(v);
        return;
    }
    idx -= S0;
    if (idx < S1) {
        int n = idx / 64, k = idx % 64;
        float v = (n < 384) ? W1[(size_t)(n / 64) * 64 * 64 + (size_t)k * 64 + (n % 64)]
                            : Ws1[(size_t)k * 64 + (n - 384)];
        Wt1[idx] = to_tf32(v);
        return;
    }
    idx -= S1;
    if (idx < S2) {
        int n = idx / 64, k = idx % 64;
        float v = (n < 384) ? W2[(size_t)(n / 64) * 64 * 64 + (size_t)k * 64 + (n % 64)]
                            : Ws2[(size_t)k * 64 + (n - 384)];
        Wt2[idx] = to_tf32(v);
        return;
    }
    idx -= S2;
    if (idx < SM) {
        int n = idx / 192, k = idx % 192;
        float v = (n < 32) ? Wm[(size_t)k * 32 + n]
                           : Wm[(size_t)192 * 32 + (size_t)k * 32 + (n - 32)];
        Wtm[idx] = to_tf32(v);
        return;
    }
    idx -= SM;
    if (idx < 448) { bias0[idx] = (idx < 64) ? b0[idx] : (idx >= 384 ? bs0[idx - 384] : 0.f); return; }
    idx -= 448;
    if (idx < 448) { bias1[idx] = (idx < 64) ? b1[idx] : (idx >= 384 ? bs1[idx - 384] : 0.f); return; }
    idx -= 448;
    if (idx < 448) { bias2[idx] = (idx < 64) ? b2[idx] : (idx >= 384 ? bs2[idx - 384] : 0.f); return; }
    idx -= 448;
    if (idx < 64) { biasm[idx] = (idx < 32) ? bm[idx] : 0.f; return; }
}

// ---------------- mma.sync tf32 GEMM (unchanged from R4) ----------------
template<int KD>
__global__ __launch_bounds__(256)
void gemm_mma(const float* __restrict__ A, const float* __restrict__ Wt,
              const float* __restrict__ biasfull, float* __restrict__ C,
              int OUT, int N) {
    constexpr int BM = 128, BN = 64, BK = 32, LDA = 36;
    __shared__ float As[BM * LDA];
    __shared__ float Bs[BN * LDA];
    const uint32_t* Asu = (const uint32_t*)As;
    const uint32_t* Bsu = (const uint32_t*)Bs;

    int tid = threadIdx.x;
    int lane = tid & 31, wid = tid >> 5;
    int wm = wid & 3, wn = wid >> 2;
    int quad = lane >> 2, qt = lane & 3;
    int br = blockIdx.x * BM;
    int colbase = blockIdx.y * BN;

    float acc[2][4][4];
    #pragma unroll
    for (int mi = 0; mi < 2; mi++)
        #pragma unroll
        for (int ni = 0; ni < 4; ni++)
            #pragma unroll
            for (int j = 0; j < 4; j++) acc[mi][ni][j] = 0.f;

    for (int k0 = 0; k0 < KD; k0 += BK) {
        #pragma unroll
        for (int t = 0; t < 4; t++) {
            int i4 = tid + 256 * t;
            int r = i4 >> 3, c4 = i4 & 7;
            int gr = br + r;
            float4 v = make_float4(0.f, 0.f, 0.f, 0.f);
            if (gr < N) v = *(const float4*)(A + (size_t)gr * KD + k0 + c4 * 4);
            v.x = to_tf32(v.x); v.y = to_tf32(v.y); v.z = to_tf32(v.z); v.w = to_tf32(v.w);
            *(float4*)(As + r * LDA + c4 * 4) = v;
        }
        #pragma unroll
        for (int t = 0; t < 2; t++) {
            int i4 = tid + 256 * t;
            int n = i4 >> 3, c4 = i4 & 7;
            float4 v = *(const float4*)(Wt + (size_t)(colbase + n) * KD + k0 + c4 * 4);
            *(float4*)(Bs + n * LDA + c4 * 4) = v;
        }
        __syncthreads();
        #pragma unroll
        for (int ks = 0; ks < 4; ks++) {
            int kk = ks * 8;
            uint32_t a[2][4];
            #pragma unroll
            for (int mi = 0; mi < 2; mi++) {
                int row = wm * 32 + mi * 16 + quad;
                a[mi][0] = Asu[row * LDA + kk + qt];
                a[mi][1] = Asu[(row + 8) * LDA + kk + qt];
                a[mi][2] = Asu[row * LDA + kk + qt + 4];
                a[mi][3] = Asu[(row + 8) * LDA + kk + qt + 4];
            }
            #pragma unroll
            for (int ni = 0; ni < 4; ni++) {
                int col = wn * 32 + ni * 8 + quad;
                uint32_t b0 = Bsu[col * LDA + kk + qt];
                uint32_t b1 = Bsu[col * LDA + kk + qt + 4];
                #pragma unroll
                for (int mi = 0; mi < 2; mi++)
                    mma_m16n8k8(acc[mi][ni], a[mi][0], a[mi][1], a[mi][2], a[mi][3], b0, b1);
            }
        }
        __syncthreads();
    }
    #pragma unroll
    for (int mi = 0; mi < 2; mi++) {
        int r0 = br + wm * 32 + mi * 16 + quad;
        #pragma unroll
        for (int ni = 0; ni < 4; ni++) {
            int cg = colbase + wn * 32 + ni * 8 + qt * 2;
            float bx = __ldg(biasfull + cg), by = __ldg(biasfull + cg + 1);
            if (r0 < N)
                *(float2*)(C + (size_t)r0 * OUT + cg) =
                    make_float2(acc[mi][ni][0] + bx, acc[mi][ni][1] + by);
            if (r0 + 8 < N)
                *(float2*)(C + (size_t)(r0 + 8) * OUT + cg) =
                    make_float2(acc[mi][ni][2] + bx, acc[mi][ni][3] + by);
        }
    }
}

// ---------------- convert: Hout[node,:] = half(dis[node] * in[node, 0:F]) ----------------
template<int F>
__global__ void conv_half(const float* __restrict__ in, int stride,
                          const float* __restrict__ dis, __half* __restrict__ out, int n) {
    constexpr int L = F / 2;
    int i = blockIdx.x * blockDim.x + threadIdx.x;
    if (i >= n * L) return;
    int node = i / L, sl = i % L;
    float2 v = ((const float2*)(in + (size_t)node * stride))[sl];
    float d = __ldg(dis + node);
    ((__half2*)out)[i] = __floats2half2_rn(d * v.x, d * v.y);
}

// ---------------- Clenshaw propagation (separable weights, fp16 gather) ----------------
// S[d] = sum_{e->d} tin_h[src_e]           (tin_h is pre-scaled by dis[src])
// v    = scale * dis[d] * S + add - sub;  relu?; + skip
// out  = v (fp32);   outh = half(dis[d] * v)  (next gather operand, optional)
template<int F>
__global__ __launch_bounds__(256)
void clenshaw_prop(const int* __restrict__ rowptr, const int* __restrict__ esrc,
                   const __half* __restrict__ tin_h,
                   const float* __restrict__ add, int add_stride,
                   const float* __restrict__ sub, int sub_stride,
                   const float* __restrict__ skip, int skip_stride,
                   const float* __restrict__ dis,
                   float* __restrict__ out, int out_stride,
                   __half* __restrict__ outh,
                   float scale, int do_relu, int n) {
    constexpr int L = F / 2;
    int gt = blockIdx.x * blockDim.x + threadIdx.x;
    int node = gt / L;
    if (node >= n) return;
    int sl = gt & (L - 1);
    int beg = __ldg(rowptr + node), end = __ldg(rowptr + node + 1);
    const __half2* tin2 = (const __half2*)tin_h;
    float2 a0 = make_float2(0.f, 0.f), a1 = make_float2(0.f, 0.f);
    float2 a2 = make_float2(0.f, 0.f), a3 = make_float2(0.f, 0.f);
    int p = beg;
    for (; p + 4 <= end; p += 4) {
        int s0 = __ldg(esrc + p), s1 = __ldg(esrc + p + 1);
        int s2 = __ldg(esrc + p + 2), s3 = __ldg(esrc + p + 3);
        float2 f0 = __half22float2(__ldg(tin2 + (size_t)s0 * L + sl));
        float2 f1 = __half22float2(__ldg(tin2 + (size_t)s1 * L + sl));
        float2 f2 = __half22float2(__ldg(tin2 + (size_t)s2 * L + sl));
        float2 f3 = __half22float2(__ldg(tin2 + (size_t)s3 * L + sl));
        a0.x += f0.x; a0.y += f0.y;
        a1.x += f1.x; a1.y += f1.y;
        a2.x += f2.x; a2.y += f2.y;
        a3.x += f3.x; a3.y += f3.y;
    }
    for (; p < end; ++p) {
        int s = __ldg(esrc + p);
        float2 f = __half22float2(__ldg(tin2 + (size_t)s * L + sl));
        a0.x += f.x; a0.y += f.y;
    }
    float d = __ldg(dis + node);
    float sd = scale * d;
    float vx = sd * (a0.x + a1.x + a2.x + a3.x);
    float vy = sd * (a0.y + a1.y + a2.y + a3.y);
    float2 ad = ((const float2*)(add + (size_t)node * add_stride))[sl];
    vx += ad.x; vy += ad.y;
    if (sub) {
        float2 s = ((const float2*)(sub + (size_t)node * sub_stride))[sl];
        vx -= s.x; vy -= s.y;
    }
    if (do_relu) { vx = fmaxf(vx, 0.f); vy = fmaxf(vy, 0.f); }
    if (skip) {
        float2 s = ((const float2*)(skip + (size_t)node * skip_stride))[sl];
        vx += s.x; vy += s.y;
    }
    ((float2*)(out + (size_t)node * out_stride))[sl] = make_float2(vx, vy);
    if (outh)
        ((__half2*)outh)[(size_t)node * L + sl] = __floats2half2_rn(d * vx, d * vy);
}

// ---------------- concat [h | x] ----------------
__global__ void concat_kernel(const float* __restrict__ h, const float* __restrict__ x,
                              float* __restrict__ cat, int N) {
    int i = blockIdx.x * blockDim.x + threadIdx.x;
    int total = N * 48;
    if (i >= total) return;
    int node = i / 48, j = i % 48;
    float4 v;
    if (j < 16) v = ((const float4*)h)[(size_t)node * 16 + j];
    else        v = ((const float4*)x)[(size_t)node * 32 + (j - 16)];
    ((float4*)cat)[i] = v;
}

// ---------------- host orchestration ----------------
static void prop64(const int* rowptr, const int* esrc, const __half* tin_h,
                   const float* add, int as, const float* sub, int ss,
                   const float* skip, int ks, const float* dis,
                   float* out, int os, __half* outh, float scale, int relu) {
    int blocks = (NN * 32 + 255) / 256;
    clenshaw_prop<64><<<blocks, 256>>>(rowptr, esrc, tin_h, add, as, sub, ss,
                                       skip, ks, dis, out, os, outh, scale, relu, NN);
}

static void cheb_layer(const float* h, int kd,
                       const float* Wt, const float* biasfull,
                       float* hout, const int* rowptr, const int* esrc,
                       const float* dis,
                       float* C, float* B0, float* B1, float* B2,
                       __half* H0, __half* H1, __half* H2, __half* H3) {
    dim3 grid((NN + 127) / 128, 7);
    if (kd == 128) gemm_mma<128><<<grid, 256>>>(h, Wt, biasfull, C, 448, NN);
    else           gemm_mma<64><<<grid, 256>>>(h, Wt, biasfull, C, 448, NN);
    // b5' = dis ⊙ c5 (fp16)
    conv_half<64><<<(NN * 32 + 255) / 256, 256>>>(C + 5 * 64, 448, dis, H3, NN);
    // b4 = c4 + 2L b5
    prop64(rowptr, esrc, H3, C + 4 * 64, 448, nullptr, 0, nullptr, 0, dis, B0, 64, H0, -2.f, 0);
    // b3 = c3 + 2L b4 - b5
    prop64(rowptr, esrc, H0, C + 3 * 64, 448, C + 5 * 64, 448, nullptr, 0, dis, B1, 64, H1, -2.f, 0);
    // b2 = c2 + 2L b3 - b4
    prop64(rowptr, esrc, H1, C + 2 * 64, 448, B0, 64, nullptr, 0, dis, B2, 64, H2, -2.f, 0);
    // b1 = c1 + 2L b2 - b3
    prop64(rowptr, esrc, H2, C + 1 * 64, 448, B1, 64, nullptr, 0, dis, B0, 64, H0, -2.f, 0);
    // h = relu(c0 + L b1 - b2) + skip
    prop64(rowptr, esrc, H0, C, 448, B2, 64, C + 6 * 64, 448, dis, hout, 64, nullptr, -1.f, 1);
}

extern "C" void kernel_launch(void* const* d_in, const int* in_sizes, int n_in,
                              void* d_out, int out_size) {
    const float* x   = (const float*)d_in[0];
    const int*   ei  = (const int*)d_in[1];
    const float* W0  = (const float*)d_in[2];
    const float* b0  = (const float*)d_in[3];
    const float* Ws0 = (const float*)d_in[4];
    const float* bs0 = (const float*)d_in[5];
    const float* W1  = (const float*)d_in[6];
    const float* b1  = (const float*)d_in[7];
    const float* Ws1 = (const float*)d_in[8];
    const float* bs1 = (const float*)d_in[9];
    const float* W2  = (const float*)d_in[10];
    const float* b2  = (const float*)d_in[11];
    const float* Ws2 = (const float*)d_in[12];
    const float* bs2 = (const float*)d_in[13];
    const float* Wm  = (const float*)d_in[14];
    const float* bm  = (const float*)d_in[15];
    float* out = (float*)d_out;

    const int* src = ei;
    const int* dst = ei + NE;

    void* p;
    cudaGetSymbolAddress(&p, g_cnt);     int*    cnt     = (int*)p;
    cudaGetSymbolAddress(&p, g_partial); int*    partial = (int*)p;
    cudaGetSymbolAddress(&p, g_rowptr);  int*    rowptr  = (int*)p;
    cudaGetSymbolAddress(&p, g_cursor);  int*    cursor  = (int*)p;
    cudaGetSymbolAddress(&p, g_dis);     float*  dis     = (float*)p;
    cudaGetSymbolAddress(&p, g_esrc);    int*    esrc    = (int*)p;
    cudaGetSymbolAddress(&p, g_C);       float*  C       = (float*)p;
    cudaGetSymbolAddress(&p, g_b0);      float*  B0      = (float*)p;
    cudaGetSymbolAddress(&p, g_b1);      float*  B1      = (float*)p;
    cudaGetSymbolAddress(&p, g_b2);      float*  B2      = (float*)p;
    cudaGetSymbolAddress(&p, g_H0);      __half* H0      = (__half*)p;
    cudaGetSymbolAddress(&p, g_H1);      __half* H1      = (__half*)p;
    cudaGetSymbolAddress(&p, g_H2);      __half* H2      = (__half*)p;
    cudaGetSymbolAddress(&p, g_H3);      __half* H3      = (__half*)p;
    cudaGetSymbolAddress(&p, g_cat);     float*  cat     = (float*)p;
    cudaGetSymbolAddress(&p, g_h1);      float*  h1      = (float*)p;
    cudaGetSymbolAddress(&p, g_h2);      float*  h2      = (float*)p;
    cudaGetSymbolAddress(&p, g_Wt0);     float*  Wt0     = (float*)p;
    cudaGetSymbolAddress(&p, g_Wt1);     float*  Wt1     = (float*)p;
    cudaGetSymbolAddress(&p, g_Wt2);     float*  Wt2     = (float*)p;
    cudaGetSymbolAddress(&p, g_Wtm);     float*  Wtm     = (float*)p;
    cudaGetSymbolAddress(&p, g_bias0);   float*  bias0   = (float*)p;
    cudaGetSymbolAddress(&p, g_bias1);   float*  bias1   = (float*)p;
    cudaGetSymbolAddress(&p, g_bias2);   float*  bias2   = (float*)p;
    cudaGetSymbolAddress(&p, g_biasm);   float*  biasm   = (float*)p;

    // ---- weight prep ----
    {
        int total = 448 * 128 + 448 * 64 + 448 * 64 + 64 * 192 + 448 * 3 + 64;
        prep_weights<<<(total + 255) / 256, 256>>>(W0, Ws0, W1, Ws1, W2, Ws2, Wm,
                                                   b0, bs0, b1, bs1, b2, bs2, bm,
                                                   Wt0, Wt1, Wt2, Wtm,
                                                   bias0, bias1, bias2, biasm);
    }

    // ---- preprocessing: degree, dis, CSR (sorted by dst; weights separable -> src only) ----
    cudaMemsetAsync(cnt, 0, NN * sizeof(int), 0);
    hist_kernel<<<(NE + 255) / 256, 256>>>(dst, cnt, NE);
    dis_kernel<<<(NN + 255) / 256, 256>>>(cnt, dis, NN);
    int nb = (NN + 255) / 256;
    reduce_kernel<<<nb, 256>>>(cnt, partial, NN);
    scanp_kernel<<<1, 512>>>(partial, nb, rowptr + NN);
    apply_kernel<<<nb, 256>>>(cnt, partial, rowptr, cursor, NN);
    fill_kernel<<<(NE + 255) / 256, 256>>>(src, dst, cursor, esrc, NE);

    // ---- 3 Kipf blocks (Clenshaw, separable-weight fp16 gather) ----
    cheb_layer(x,  128, Wt0, bias0, h1, rowptr, esrc, dis, C, B0, B1, B2, H0, H1, H2, H3);
    cheb_layer(h1,  64, Wt1, bias1, h2, rowptr, esrc, dis, C, B0, B1, B2, H0, H1, H2, H3);
    cheb_layer(h2,  64, Wt2, bias2, h1, rowptr, esrc, dis, C, B0, B1, B2, H0, H1, H2, H3);

    // ---- mix head: concat(h, x) -> ChebConv K=2 -> out ----
    concat_kernel<<<(NN * 48 + 255) / 256, 256>>>(h1, x, cat, NN);
    {
        dim3 grid((NN + 127) / 128, 1);
        gemm_mma<192><<<grid, 256>>>(cat, Wtm, biasm, B0, 64, NN);
        // c1' = dis ⊙ c1 (fp16, 32-d)
        conv_half<32><<<(NN * 16 + 255) / 256, 256>>>(B0 + 32, 64, dis, H0, NN);
        // out = c0 + L c1
        int blocks = (NN * 16 + 255) / 256;
        clenshaw_prop<32><<<blocks, 256>>>(rowptr, esrc, H0, B0, 64, nullptr, 0,
                                           nullptr, 0, dis, out, 32, nullptr, -1.f, 0, NN);
    }
}

// round 6
// speedup vs baseline: 2.1354x; 1.1253x over previous
#include <cuda_runtime.h>
#include <cuda_fp16.h>
#include <cstdint>

#define NN 100000
#define NE 3200000
#define NH 64

// ---------------- scratch (__device__ globals: allocation-free) ----------------
__device__ int    g_cnt[NN];
__device__ int    g_partial[512];
__device__ int    g_rowptr[NN + 1];
__device__ int    g_cursor[NN];
__device__ float  g_dis[NN];
__device__ int    g_esrc[NE];             // CSR-by-dst src indices (weights separable)
__device__ float  g_C[(size_t)NN * 448];  // fused GEMM output: c_0..c_5 | skip
__device__ float  g_b0[NN * NH];
__device__ float  g_b1[NN * NH];
__device__ float  g_b2[NN * NH];
__device__ __half g_H0[NN * NH];          // pre-scaled (dis⊙) fp16 gather buffers
__device__ __half g_H1[NN * NH];
__device__ __half g_H2[NN * NH];
__device__ __half g_H3[NN * NH];
__device__ float  g_h1[NN * NH];
__device__ float  g_h2[NN * NH];
// tf32 transposed weights (rows = output col, contiguous K) + fused bias vectors
__device__ float g_Wt0[448 * 128];
__device__ float g_Wt1[448 * 64];
__device__ float g_Wt2[448 * 64];
__device__ float g_Wtm[64 * 192];
__device__ float g_bias0[448];
__device__ float g_bias1[448];
__device__ float g_bias2[448];
__device__ float g_biasm[64];

__device__ __forceinline__ float to_tf32(float v) {
    uint32_t u;
    asm("cvt.rna.tf32.f32 %0, %1;" : "=r"(u) : "f"(v));
    return __uint_as_float(u);
}

__device__ __forceinline__ void mma_m16n8k8(float* c, uint32_t a0, uint32_t a1,
                                            uint32_t a2, uint32_t a3,
                                            uint32_t b0, uint32_t b1) {
    asm volatile(
        "mma.sync.aligned.m16n8k8.row.col.f32.tf32.tf32.f32 "
        "{%0,%1,%2,%3}, {%4,%5,%6,%7}, {%8,%9}, {%0,%1,%2,%3};"
        : "+f"(c[0]), "+f"(c[1]), "+f"(c[2]), "+f"(c[3])
        : "r"(a0), "r"(a1), "r"(a2), "r"(a3), "r"(b0), "r"(b1));
}

// ---------------- graph preprocessing ----------------
__global__ void hist_kernel(const int* __restrict__ dst, int* __restrict__ cnt, int E) {
    int i = blockIdx.x * blockDim.x + threadIdx.x;
    if (i < E) atomicAdd(&cnt[dst[i]], 1);
}

__global__ void reduce_kernel(const int* __restrict__ cnt, int* __restrict__ partial, int n) {
    __shared__ int s[8];
    int i = blockIdx.x * 256 + threadIdx.x;
    int v = (i < n) ? cnt[i] : 0;
    #pragma unroll
    for (int o = 16; o; o >>= 1) v += __shfl_down_sync(0xffffffffu, v, o);
    if ((threadIdx.x & 31) == 0) s[threadIdx.x >> 5] = v;
    __syncthreads();
    if (threadIdx.x < 8) {
        int t = s[threadIdx.x];
        #pragma unroll
        for (int o = 4; o; o >>= 1) t += __shfl_down_sync(0xffu, t, o);
        if (threadIdx.x == 0) partial[blockIdx.x] = t;
    }
}

__global__ void scanp_kernel(int* __restrict__ partial, int nb, int* __restrict__ total_out) {
    __shared__ int ws[16];
    int tid = threadIdx.x, lane = tid & 31, w = tid >> 5;
    int v = (tid < nb) ? partial[tid] : 0;
    int x = v;
    #pragma unroll
    for (int o = 1; o < 32; o <<= 1) {
        int y = __shfl_up_sync(0xffffffffu, x, o);
        if (lane >= o) x += y;
    }
    if (lane == 31) ws[w] = x;
    __syncthreads();
    if (w == 0 && lane < 16) {
        int t = ws[lane];
        #pragma unroll
        for (int o = 1; o < 16; o <<= 1) {
            int y = __shfl_up_sync(0xffffu, t, o);
            if (lane >= o) t += y;
        }
        ws[lane] = t;
    }
    __syncthreads();
    int excl = x - v + (w ? ws[w - 1] : 0);
    if (tid < nb) partial[tid] = excl;
    if (tid == nb - 1) total_out[0] = excl + v;
}

// block-scan apply + fused dis = rsqrt(deg)
__global__ void apply_kernel(const int* __restrict__ cnt, const int* __restrict__ partial,
                             int* __restrict__ rowptr, int* __restrict__ cursor,
                             float* __restrict__ dis, int n) {
    __shared__ int ws[8];
    int i = blockIdx.x * 256 + threadIdx.x;
    int lane = threadIdx.x & 31, w = threadIdx.x >> 5;
    int v = (i < n) ? cnt[i] : 0;
    int x = v;
    #pragma unroll
    for (int o = 1; o < 32; o <<= 1) {
        int y = __shfl_up_sync(0xffffffffu, x, o);
        if (lane >= o) x += y;
    }
    if (lane == 31) ws[w] = x;
    __syncthreads();
    if (w == 0 && lane < 8) {
        int t = ws[lane];
        #pragma unroll
        for (int o = 1; o < 8; o <<= 1) {
            int y = __shfl_up_sync(0xffu, t, o);
            if (lane >= o) t += y;
        }
        ws[lane] = t;
    }
    __syncthreads();
    int excl = x - v + (w ? ws[w - 1] : 0) + partial[blockIdx.x];
    if (i < n) {
        rowptr[i] = excl;
        cursor[i] = excl;
        dis[i] = v > 0 ? rsqrtf((float)v) : 0.0f;
    }
}

__global__ void fill_kernel(const int* __restrict__ src, const int* __restrict__ dst,
                            int* __restrict__ cursor, int* __restrict__ esrc, int E) {
    int i = blockIdx.x * blockDim.x + threadIdx.x;
    if (i < E) {
        int d = dst[i];
        int pos = atomicAdd(&cursor[d], 1);
        esrc[pos] = src[i];
    }
}

// ---------------- weight prep: transpose to [OUT][KD], cvt to tf32; fused biases ----------------
__global__ void prep_weights(const float* __restrict__ W0, const float* __restrict__ Ws0,
                             const float* __restrict__ W1, const float* __restrict__ Ws1,
                             const float* __restrict__ W2, const float* __restrict__ Ws2,
                             const float* __restrict__ Wm,
                             const float* __restrict__ b0, const float* __restrict__ bs0,
                             const float* __restrict__ b1, const float* __restrict__ bs1,
                             const float* __restrict__ b2, const float* __restrict__ bs2,
                             const float* __restrict__ bm,
                             float* __restrict__ Wt0, float* __restrict__ Wt1,
                             float* __restrict__ Wt2, float* __restrict__ Wtm,
                             float* __restrict__ bias0, float* __restrict__ bias1,
                             float* __restrict__ bias2, float* __restrict__ biasm) {
    int idx = blockIdx.x * blockDim.x + threadIdx.x;
    const int S0 = 448 * 128, S1 = 448 * 64, S2 = 448 * 64, SM = 64 * 192;
    if (idx < S0) {
        int n = idx / 128, k = idx % 128;
        float v = (n < 384) ? W0[(size_t)(n / 64) * 128 * 64 + (size_t)k * 64 + (n % 64)]
                            : Ws0[(size_t)k * 64 + (n - 384)];
        Wt0[idx] = to_tf32(v);
        return;
    }
    idx -= S0;
    if (idx < S1) {
        int n = idx / 64, k = idx % 64;
        float v = (n < 384) ? W1[(size_t)(n / 64) * 64 * 64 + (size_t)k * 64 + (n % 64)]
                            : Ws1[(size_t)k * 64 + (n - 384)];
        Wt1[idx] = to_tf32(v);
        return;
    }
    idx -= S1;
    if (idx < S2) {
        int n = idx / 64, k = idx % 64;
        float v = (n < 384) ? W2[(size_t)(n / 64) * 64 * 64 + (size_t)k * 64 + (n % 64)]
                            : Ws2[(size_t)k * 64 + (n - 384)];
        Wt2[idx] = to_tf32(v);
        return;
    }
    idx -= S2;
    if (idx < SM) {
        int n = idx / 192, k = idx % 192;
        float v = (n < 32) ? Wm[(size_t)k * 32 + n]
                           : Wm[(size_t)192 * 32 + (size_t)k * 32 + (n - 32)];
        Wtm[idx] = to_tf32(v);
        return;
    }
    idx -= SM;
    if (idx < 448) { bias0[idx] = (idx < 64) ? b0[idx] : (idx >= 384 ? bs0[idx - 384] : 0.f); return; }
    idx -= 448;
    if (idx < 448) { bias1[idx] = (idx < 64) ? b1[idx] : (idx >= 384 ? bs1[idx - 384] : 0.f); return; }
    idx -= 448;
    if (idx < 448) { bias2[idx] = (idx < 64) ? b2[idx] : (idx >= 384 ? bs2[idx - 384] : 0.f); return; }
    idx -= 448;
    if (idx < 64) { biasm[idx] = (idx < 32) ? bm[idx] : 0.f; return; }
}

// ---------------- mma.sync tf32 GEMM (register-prefetch pipelined) ----------------
// A operand split: cols [0,SPLIT) from A (row stride SPLIT), cols [SPLIT,KD) from A2
// (row stride KD-SPLIT). SPLIT==KD -> single source. Epilogue optionally writes the
// fp16 dis-scaled copy of columns [WLO,WHI) to Hout (the next prop's gather operand).
template<int KD, int SPLIT, int WLO, int WHI>
__global__ __launch_bounds__(256)
void gemm_mma(const float* __restrict__ A, const float* __restrict__ A2,
              const float* __restrict__ Wt, const float* __restrict__ biasfull,
              const float* __restrict__ dis, __half* __restrict__ Hout,
              float* __restrict__ C, int OUT, int N) {
    constexpr int BM = 128, BN = 64, LDA = 36;
    constexpr int NKT = KD / 32;
    constexpr int A2S = (KD > SPLIT) ? (KD - SPLIT) : 1;  // A2 row stride
    __shared__ float As[BM * LDA];
    __shared__ float Bs[BN * LDA];
    const uint32_t* Asu = (const uint32_t*)As;
    const uint32_t* Bsu = (const uint32_t*)Bs;

    int tid = threadIdx.x;
    int lane = tid & 31, wid = tid >> 5;
    int wm = wid & 3, wn = wid >> 2;
    int quad = lane >> 2, qt = lane & 3;
    int br = blockIdx.x * BM;
    int colbase = blockIdx.y * BN;

    float acc[2][4][4];
    #pragma unroll
    for (int mi = 0; mi < 2; mi++)
        #pragma unroll
        for (int ni = 0; ni < 4; ni++)
            #pragma unroll
            for (int j = 0; j < 4; j++) acc[mi][ni][j] = 0.f;

    float4 ra[4], rb[2];
    int ar[4], ac4[4], bn_[2], bc4[2];
    #pragma unroll
    for (int t = 0; t < 4; t++) {
        int i4 = tid + 256 * t;
        ar[t] = i4 >> 3; ac4[t] = i4 & 7;
    }
    #pragma unroll
    for (int t = 0; t < 2; t++) {
        int i4 = tid + 256 * t;
        bn_[t] = i4 >> 3; bc4[t] = i4 & 7;
    }

    auto load_tile = [&](int k0) {
        #pragma unroll
        for (int t = 0; t < 4; t++) {
            int gr = br + ar[t];
            int col = k0 + ac4[t] * 4;
            float4 v = make_float4(0.f, 0.f, 0.f, 0.f);
            if (gr < N) {
                if (SPLIT == KD || col < SPLIT)
                    v = *(const float4*)(A + (size_t)gr * SPLIT + col);
                else
                    v = *(const float4*)(A2 + (size_t)gr * A2S + (col - SPLIT));
            }
            v.x = to_tf32(v.x); v.y = to_tf32(v.y); v.z = to_tf32(v.z); v.w = to_tf32(v.w);
            ra[t] = v;
        }
        #pragma unroll
        for (int t = 0; t < 2; t++)
            rb[t] = *(const float4*)(Wt + (size_t)(colbase + bn_[t]) * KD + k0 + bc4[t] * 4);
    };

    load_tile(0);
    #pragma unroll
    for (int kt = 0; kt < NKT; kt++) {
        // stage regs -> smem
        #pragma unroll
        for (int t = 0; t < 4; t++)
            *(float4*)(As + ar[t] * LDA + ac4[t] * 4) = ra[t];
        #pragma unroll
        for (int t = 0; t < 2; t++)
            *(float4*)(Bs + bn_[t] * LDA + bc4[t] * 4) = rb[t];
        __syncthreads();
        if (kt + 1 < NKT) load_tile((kt + 1) * 32);   // overlapped with MMA below
        #pragma unroll
        for (int ks = 0; ks < 4; ks++) {
            int kk = ks * 8;
            uint32_t a[2][4];
            #pragma unroll
            for (int mi = 0; mi < 2; mi++) {
                int row = wm * 32 + mi * 16 + quad;
                a[mi][0] = Asu[row * LDA + kk + qt];
                a[mi][1] = Asu[(row + 8) * LDA + kk + qt];
                a[mi][2] = Asu[row * LDA + kk + qt + 4];
                a[mi][3] = Asu[(row + 8) * LDA + kk + qt + 4];
            }
            #pragma unroll
            for (int ni = 0; ni < 4; ni++) {
                int col = wn * 32 + ni * 8 + quad;
                uint32_t b0 = Bsu[col * LDA + kk + qt];
                uint32_t b1 = Bsu[col * LDA + kk + qt + 4];
                #pragma unroll
                for (int mi = 0; mi < 2; mi++)
                    mma_m16n8k8(acc[mi][ni], a[mi][0], a[mi][1], a[mi][2], a[mi][3], b0, b1);
            }
        }
        __syncthreads();
    }
    // epilogue: bias + store; optional fused fp16 dis-scaled copy for [WLO,WHI)
    #pragma unroll
    for (int mi = 0; mi < 2; mi++) {
        int r0 = br + wm * 32 + mi * 16 + quad;
        float d0 = 0.f, d1 = 0.f;
        if (WHI > WLO) {
            if (r0 < N) d0 = __ldg(dis + r0);
            if (r0 + 8 < N) d1 = __ldg(dis + r0 + 8);
        }
        #pragma unroll
        for (int ni = 0; ni < 4; ni++) {
            int cg = colbase + wn * 32 + ni * 8 + qt * 2;
            float bx = __ldg(biasfull + cg), by = __ldg(biasfull + cg + 1);
            float v0x = acc[mi][ni][0] + bx, v0y = acc[mi][ni][1] + by;
            float v1x = acc[mi][ni][2] + bx, v1y = acc[mi][ni][3] + by;
            bool inw = (WHI > WLO) && cg >= WLO && cg < WHI;
            if (r0 < N) {
                *(float2*)(C + (size_t)r0 * OUT + cg) = make_float2(v0x, v0y);
                if (inw)
                    ((__half2*)Hout)[(size_t)r0 * ((WHI - WLO) / 2) + (cg - WLO) / 2] =
                        __floats2half2_rn(d0 * v0x, d0 * v0y);
            }
            if (r0 + 8 < N) {
                *(float2*)(C + (size_t)(r0 + 8) * OUT + cg) = make_float2(v1x, v1y);
                if (inw)
                    ((__half2*)Hout)[(size_t)(r0 + 8) * ((WHI - WLO) / 2) + (cg - WLO) / 2] =
                        __floats2half2_rn(d1 * v1x, d1 * v1y);
            }
        }
    }
}

// ---------------- Clenshaw propagation (separable weights, fp16 gather, unroll 8) ----------------
template<int F>
__global__ __launch_bounds__(256)
void clenshaw_prop(const int* __restrict__ rowptr, const int* __restrict__ esrc,
                   const __half* __restrict__ tin_h,
                   const float* __restrict__ add, int add_stride,
                   const float* __restrict__ sub, int sub_stride,
                   const float* __restrict__ skip, int skip_stride,
                   const float* __restrict__ dis,
                   float* __restrict__ out, int out_stride,
                   __half* __restrict__ outh,
                   float scale, int do_relu, int n) {
    constexpr int L = F / 2;
    int gt = blockIdx.x * blockDim.x + threadIdx.x;
    int node = gt / L;
    if (node >= n) return;
    int sl = gt & (L - 1);
    int beg = __ldg(rowptr + node), end = __ldg(rowptr + node + 1);
    const __half2* tin2 = (const __half2*)tin_h;
    float2 a0 = make_float2(0.f, 0.f), a1 = make_float2(0.f, 0.f);
    float2 a2 = make_float2(0.f, 0.f), a3 = make_float2(0.f, 0.f);
    int p = beg;
    for (; p + 8 <= end; p += 8) {
        int s0 = __ldg(esrc + p),     s1 = __ldg(esrc + p + 1);
        int s2 = __ldg(esrc + p + 2), s3 = __ldg(esrc + p + 3);
        int s4 = __ldg(esrc + p + 4), s5 = __ldg(esrc + p + 5);
        int s6 = __ldg(esrc + p + 6), s7 = __ldg(esrc + p + 7);
        float2 f0 = __half22float2(__ldg(tin2 + (size_t)s0 * L + sl));
        float2 f1 = __half22float2(__ldg(tin2 + (size_t)s1 * L + sl));
        float2 f2 = __half22float2(__ldg(tin2 + (size_t)s2 * L + sl));
        float2 f3 = __half22float2(__ldg(tin2 + (size_t)s3 * L + sl));
        float2 f4 = __half22float2(__ldg(tin2 + (size_t)s4 * L + sl));
        float2 f5 = __half22float2(__ldg(tin2 + (size_t)s5 * L + sl));
        float2 f6 = __half22float2(__ldg(tin2 + (size_t)s6 * L + sl));
        float2 f7 = __half22float2(__ldg(tin2 + (size_t)s7 * L + sl));
        a0.x += f0.x + f4.x; a0.y += f0.y + f4.y;
        a1.x += f1.x + f5.x; a1.y += f1.y + f5.y;
        a2.x += f2.x + f6.x; a2.y += f2.y + f6.y;
        a3.x += f3.x + f7.x; a3.y += f3.y + f7.y;
    }
    for (; p < end; ++p) {
        int s = __ldg(esrc + p);
        float2 f = __half22float2(__ldg(tin2 + (size_t)s * L + sl));
        a0.x += f.x; a0.y += f.y;
    }
    float d = __ldg(dis + node);
    float sd = scale * d;
    float vx = sd * ((a0.x + a1.x) + (a2.x + a3.x));
    float vy = sd * ((a0.y + a1.y) + (a2.y + a3.y));
    float2 ad = ((const float2*)(add + (size_t)node * add_stride))[sl];
    vx += ad.x; vy += ad.y;
    if (sub) {
        float2 s = ((const float2*)(sub + (size_t)node * sub_stride))[sl];
        vx -= s.x; vy -= s.y;
    }
    if (do_relu) { vx = fmaxf(vx, 0.f); vy = fmaxf(vy, 0.f); }
    if (skip) {
        float2 s = ((const float2*)(skip + (size_t)node * skip_stride))[sl];
        vx += s.x; vy += s.y;
    }
    ((float2*)(out + (size_t)node * out_stride))[sl] = make_float2(vx, vy);
    if (outh)
        ((__half2*)outh)[(size_t)node * L + sl] = __floats2half2_rn(d * vx, d * vy);
}

// ---------------- host orchestration ----------------
static void prop64(const int* rowptr, const int* esrc, const __half* tin_h,
                   const float* add, int as, const float* sub, int ss,
                   const float* skip, int ks, const float* dis,
                   float* out, int os, __half* outh, float scale, int relu) {
    int blocks = (NN * 32 + 255) / 256;
    clenshaw_prop<64><<<blocks, 256>>>(rowptr, esrc, tin_h, add, as, sub, ss,
                                       skip, ks, dis, out, os, outh, scale, relu, NN);
}

static void cheb_layer(const float* h, int kd,
                       const float* Wt, const float* biasfull,
                       float* hout, const int* rowptr, const int* esrc,
                       const float* dis,
                       float* C, float* B0, float* B1, float* B2,
                       __half* H0, __half* H1, __half* H2, __half* H3) {
    dim3 grid((NN + 127) / 128, 7);
    // fused GEMM also emits H3 = dis ⊙ c5 in fp16 (cols [320,384))
    if (kd == 128)
        gemm_mma<128, 128, 320, 384><<<grid, 256>>>(h, nullptr, Wt, biasfull, dis, H3, C, 448, NN);
    else
        gemm_mma<64, 64, 320, 384><<<grid, 256>>>(h, nullptr, Wt, biasfull, dis, H3, C, 448, NN);
    // Clenshaw recursion (b5 = c5 lives in C, stride 448)
    prop64(rowptr, esrc, H3, C + 4 * 64, 448, nullptr, 0, nullptr, 0, dis, B0, 64, H0, -2.f, 0);
    prop64(rowptr, esrc, H0, C + 3 * 64, 448, C + 5 * 64, 448, nullptr, 0, dis, B1, 64, H1, -2.f, 0);
    prop64(rowptr, esrc, H1, C + 2 * 64, 448, B0, 64, nullptr, 0, dis, B2, 64, H2, -2.f, 0);
    prop64(rowptr, esrc, H2, C + 1 * 64, 448, B1, 64, nullptr, 0, dis, B0, 64, H0, -2.f, 0);
    prop64(rowptr, esrc, H0, C, 448, B2, 64, C + 6 * 64, 448, dis, hout, 64, nullptr, -1.f, 1);
}

extern "C" void kernel_launch(void* const* d_in, const int* in_sizes, int n_in,
                              void* d_out, int out_size) {
    const float* x   = (const float*)d_in[0];
    const int*   ei  = (const int*)d_in[1];
    const float* W0  = (const float*)d_in[2];
    const float* b0  = (const float*)d_in[3];
    const float* Ws0 = (const float*)d_in[4];
    const float* bs0 = (const float*)d_in[5];
    const float* W1  = (const float*)d_in[6];
    const float* b1  = (const float*)d_in[7];
    const float* Ws1 = (const float*)d_in[8];
    const float* bs1 = (const float*)d_in[9];
    const float* W2  = (const float*)d_in[10];
    const float* b2  = (const float*)d_in[11];
    const float* Ws2 = (const float*)d_in[12];
    const float* bs2 = (const float*)d_in[13];
    const float* Wm  = (const float*)d_in[14];
    const float* bm  = (const float*)d_in[15];
    float* out = (float*)d_out;

    const int* src = ei;
    const int* dst = ei + NE;

    void* p;
    cudaGetSymbolAddress(&p, g_cnt);     int*    cnt     = (int*)p;
    cudaGetSymbolAddress(&p, g_partial); int*    partial = (int*)p;
    cudaGetSymbolAddress(&p, g_rowptr);  int*    rowptr  = (int*)p;
    cudaGetSymbolAddress(&p, g_cursor);  int*    cursor  = (int*)p;
    cudaGetSymbolAddress(&p, g_dis);     float*  dis     = (float*)p;
    cudaGetSymbolAddress(&p, g_esrc);    int*    esrc    = (int*)p;
    cudaGetSymbolAddress(&p, g_C);       float*  C       = (float*)p;
    cudaGetSymbolAddress(&p, g_b0);      float*  B0      = (float*)p;
    cudaGetSymbolAddress(&p, g_b1);      float*  B1      = (float*)p;
    cudaGetSymbolAddress(&p, g_b2);      float*  B2      = (float*)p;
    cudaGetSymbolAddress(&p, g_H0);      __half* H0      = (__half*)p;
    cudaGetSymbolAddress(&p, g_H1);      __half* H1      = (__half*)p;
    cudaGetSymbolAddress(&p, g_H2);      __half* H2      = (__half*)p;
    cudaGetSymbolAddress(&p, g_H3);      __half* H3      = (__half*)p;
    cudaGetSymbolAddress(&p, g_h1);      float*  h1      = (float*)p;
    cudaGetSymbolAddress(&p, g_h2);      float*  h2      = (float*)p;
    cudaGetSymbolAddress(&p, g_Wt0);     float*  Wt0     = (float*)p;
    cudaGetSymbolAddress(&p, g_Wt1);     float*  Wt1     = (float*)p;
    cudaGetSymbolAddress(&p, g_Wt2);     float*  Wt2     = (float*)p;
    cudaGetSymbolAddress(&p, g_Wtm);     float*  Wtm     = (float*)p;
    cudaGetSymbolAddress(&p, g_bias0);   float*  bias0   = (float*)p;
    cudaGetSymbolAddress(&p, g_bias1);   float*  bias1   = (float*)p;
    cudaGetSymbolAddress(&p, g_bias2);   float*  bias2   = (float*)p;
    cudaGetSymbolAddress(&p, g_biasm);   float*  biasm   = (float*)p;

    // ---- weight prep ----
    {
        int total = 448 * 128 + 448 * 64 + 448 * 64 + 64 * 192 + 448 * 3 + 64;
        prep_weights<<<(total + 255) / 256, 256>>>(W0, Ws0, W1, Ws1, W2, Ws2, Wm,
                                                   b0, bs0, b1, bs1, b2, bs2, bm,
                                                   Wt0, Wt1, Wt2, Wtm,
                                                   bias0, bias1, bias2, biasm);
    }

    // ---- preprocessing: degree + dis, CSR (sorted by dst; separable weights -> src only) ----
    cudaMemsetAsync(cnt, 0, NN * sizeof(int), 0);
    hist_kernel<<<(NE + 255) / 256, 256>>>(dst, cnt, NE);
    int nb = (NN + 255) / 256;
    reduce_kernel<<<nb, 256>>>(cnt, partial, NN);
    scanp_kernel<<<1, 512>>>(partial, nb, rowptr + NN);
    apply_kernel<<<nb, 256>>>(cnt, partial, rowptr, cursor, dis, NN);
    fill_kernel<<<(NE + 255) / 256, 256>>>(src, dst, cursor, esrc, NE);

    // ---- 3 Kipf blocks (Clenshaw, separable-weight fp16 gather) ----
    cheb_layer(x,  128, Wt0, bias0, h1, rowptr, esrc, dis, C, B0, B1, B2, H0, H1, H2, H3);
    cheb_layer(h1,  64, Wt1, bias1, h2, rowptr, esrc, dis, C, B0, B1, B2, H0, H1, H2, H3);
    cheb_layer(h2,  64, Wt2, bias2, h1, rowptr, esrc, dis, C, B0, B1, B2, H0, H1, H2, H3);

    // ---- mix head: dual-source GEMM (h1 | x) -> ChebConv K=2 -> out ----
    {
        dim3 grid((NN + 127) / 128, 1);
        // Cmix[N,64] = [h1 | x] @ [Wm0 | Wm1]; fused H0 = dis ⊙ c1 (cols [32,64)) in fp16
        gemm_mma<192, 64, 32, 64><<<grid, 256>>>(h1, x, Wtm, biasm, dis, H0, B0, 64, NN);
        // out = c0 + L c1
        int blocks = (NN * 16 + 255) / 256;
        clenshaw_prop<32><<<blocks, 256>>>(rowptr, esrc, H0, B0, 64, nullptr, 0,
                                           nullptr, 0, dis, out, 32, nullptr, -1.f, 0, NN);
    }
}